// round 1
// baseline (speedup 1.0000x reference)
#include <cuda_runtime.h>
#include <cuda_bf16.h>

// Problem constants (fixed shapes for this problem)
#define N_NODES 40000
#define N_EDGES 640000
#define D 128

// ---------------- device scratch (no allocations allowed) ----------------
__device__ float g_h[N_NODES * D];        // LayerNorm output
__device__ float g_P[N_NODES * 2 * D];    // [h@Wa | h@Wb] per node
__device__ float g_msum[N_NODES * D];     // scatter sum of messages
__device__ float g_cnt[N_NODES];          // edge counts per src node

// ---------------- helpers ----------------
__device__ __forceinline__ float silu_f(float x) {
    return x / (1.0f + __expf(-x));
}

__device__ __forceinline__ unsigned long long pack2(float x, float y) {
    unsigned long long r;
    asm("mov.b64 %0, {%1, %2};" : "=l"(r) : "f"(x), "f"(y));
    return r;
}

__device__ __forceinline__ void fma2(unsigned long long &d,
                                     unsigned long long a,
                                     unsigned long long b) {
    // packed fp32x2 FMA (Blackwell dual-fp32 path; only reachable via PTX)
    asm("fma.rn.f32x2 %0, %1, %2, %0;" : "+l"(d) : "l"(a), "l"(b));
}

__device__ __forceinline__ float2 unpack2(unsigned long long v) {
    float lo, hi;
    asm("mov.b64 {%0, %1}, %2;" : "=f"(lo), "=f"(hi) : "l"(v));
    return make_float2(lo, hi);
}

__device__ __forceinline__ void unpack_acc8(const unsigned long long a[4], float x[8]) {
    float2 t;
    t = unpack2(a[0]); x[0] = t.x; x[1] = t.y;
    t = unpack2(a[1]); x[2] = t.x; x[3] = t.y;
    t = unpack2(a[2]); x[4] = t.x; x[5] = t.y;
    t = unpack2(a[3]); x[6] = t.x; x[7] = t.y;
}

__device__ __forceinline__ void red_add4(float* p, float a, float b, float c, float d) {
    asm volatile("red.global.add.v4.f32 [%0], {%1, %2, %3, %4};"
                 :: "l"(p), "f"(a), "f"(b), "f"(c), "f"(d) : "memory");
}

// 16-k-step micro GEMM: acc[4 rows][4 col-pairs] over a 128x128 tile.
// sA layout: [k][row], stride 132 (padded).  sWk: [k][col], stride 128 (chunk base).
__device__ __forceinline__ void mma16(const float* __restrict__ sA,
                                      const float* __restrict__ sWk,
                                      int rg, int cg,
                                      unsigned long long acc[4][4]) {
#pragma unroll
    for (int k = 0; k < 16; ++k) {
        float4 a4 = *reinterpret_cast<const float4*>(sA + k * 132 + rg * 4);
        const float* wr = sWk + k * 128 + cg * 8;
        ulonglong2 b01 = *reinterpret_cast<const ulonglong2*>(wr);
        ulonglong2 b23 = *reinterpret_cast<const ulonglong2*>(wr + 4);
        float a[4] = {a4.x, a4.y, a4.z, a4.w};
#pragma unroll
        for (int r = 0; r < 4; ++r) {
            unsigned long long ap = pack2(a[r], a[r]);
            fma2(acc[r][0], ap, b01.x);
            fma2(acc[r][1], ap, b01.y);
            fma2(acc[r][2], ap, b23.x);
            fma2(acc[r][3], ap, b23.y);
        }
    }
}

// Second GEMM: A held in smem as [row][k] (stride 132), scalar column reads
// broadcast across the 16 cg lanes (conflict-free).
__device__ __forceinline__ void gemm2_128(const float* __restrict__ sM1,
                                          const float* __restrict__ sW2,
                                          int rg, int cg,
                                          unsigned long long acc[4][4]) {
    const int r0 = rg * 4;
#pragma unroll 8
    for (int k = 0; k < 128; ++k) {
        const float* wr = sW2 + k * 128 + cg * 8;
        ulonglong2 b01 = *reinterpret_cast<const ulonglong2*>(wr);
        ulonglong2 b23 = *reinterpret_cast<const ulonglong2*>(wr + 4);
#pragma unroll
        for (int r = 0; r < 4; ++r) {
            float a = sM1[(r0 + r) * 132 + k];
            unsigned long long ap = pack2(a, a);
            fma2(acc[r][0], ap, b01.x);
            fma2(acc[r][1], ap, b01.y);
            fma2(acc[r][2], ap, b23.x);
            fma2(acc[r][3], ap, b23.y);
        }
    }
}

// ---------------- kernel 1: zero scratch ----------------
__global__ void zero_kernel() {
    int i = blockIdx.x * blockDim.x + threadIdx.x;
    const int total4 = N_NODES * D / 4;
    if (i < total4) reinterpret_cast<float4*>(g_msum)[i] = make_float4(0.f, 0.f, 0.f, 0.f);
    if (i < N_NODES) g_cnt[i] = 0.0f;
}

// ---------------- kernel 2: LayerNorm (one warp per node row) ----------------
__global__ void ln_kernel(const float* __restrict__ x,
                          const float* __restrict__ gamma,
                          const float* __restrict__ beta) {
    int warp = threadIdx.x >> 5;
    int lane = threadIdx.x & 31;
    int n = blockIdx.x * 8 + warp;   // N divisible by 8 * 5000
    float4 v = *reinterpret_cast<const float4*>(x + (size_t)n * D + lane * 4);
    float s = v.x + v.y + v.z + v.w;
#pragma unroll
    for (int o = 16; o > 0; o >>= 1) s += __shfl_xor_sync(0xffffffffu, s, o);
    float mu = s * (1.0f / D);
    float d0 = v.x - mu, d1 = v.y - mu, d2 = v.z - mu, d3 = v.w - mu;
    float ss = d0 * d0 + d1 * d1 + d2 * d2 + d3 * d3;
#pragma unroll
    for (int o = 16; o > 0; o >>= 1) ss += __shfl_xor_sync(0xffffffffu, ss, o);
    float rs = rsqrtf(ss * (1.0f / D) + 1e-5f);
    float4 g = *reinterpret_cast<const float4*>(gamma + lane * 4);
    float4 b = *reinterpret_cast<const float4*>(beta + lane * 4);
    float4 o4;
    o4.x = d0 * rs * g.x + b.x;
    o4.y = d1 * rs * g.y + b.y;
    o4.z = d2 * rs * g.z + b.z;
    o4.w = d3 * rs * g.w + b.w;
    *reinterpret_cast<float4*>(g_h + (size_t)n * D + lane * 4) = o4;
}

// ---------------- kernel 3: node projections P = h @ [Wa | Wb] ----------------
__global__ __launch_bounds__(512, 1)
void pnode_kernel(const float* __restrict__ msg_w1) {
    extern __shared__ float smem[];
    float* sW = smem;            // 16384 floats
    float* sA = sW + 16384;      // 16*132

    const int tid = threadIdx.x;
    const int rg = tid >> 4;
    const int cg = tid & 15;
    const int n0 = blockIdx.x * 128;
    const int half = blockIdx.y; // 0 -> Wa (rows 0..127), 1 -> Wb (rows 128..255)

    const float4* w4 = reinterpret_cast<const float4*>(msg_w1 + half * 128 * 128);
#pragma unroll
    for (int i = 0; i < 8; ++i)
        reinterpret_cast<float4*>(sW)[tid + i * 512] = w4[tid + i * 512];

    unsigned long long acc[4][4];
#pragma unroll
    for (int r = 0; r < 4; ++r)
#pragma unroll
        for (int p = 0; p < 4; ++p) acc[r][p] = 0ull;

    const int arow = tid >> 2;
    const int akk  = (tid & 3) * 4;

    for (int kc = 0; kc < 8; ++kc) {
        if (kc) __syncthreads();
        int n = n0 + arow;
        float4 v = make_float4(0.f, 0.f, 0.f, 0.f);
        if (n < N_NODES)
            v = *reinterpret_cast<const float4*>(g_h + (size_t)n * 128 + kc * 16 + akk);
        sA[(akk + 0) * 132 + arow] = v.x;
        sA[(akk + 1) * 132 + arow] = v.y;
        sA[(akk + 2) * 132 + arow] = v.z;
        sA[(akk + 3) * 132 + arow] = v.w;
        __syncthreads();
        mma16(sA, sW + kc * 16 * 128, rg, cg, acc);
    }

#pragma unroll
    for (int r = 0; r < 4; ++r) {
        int n = n0 + rg * 4 + r;
        if (n >= N_NODES) continue;
        float x[8];
        unpack_acc8(acc[r], x);
        float* dst = g_P + (size_t)n * 256 + half * 128 + cg * 8;
        *reinterpret_cast<float4*>(dst)     = make_float4(x[0], x[1], x[2], x[3]);
        *reinterpret_cast<float4*>(dst + 4) = make_float4(x[4], x[5], x[6], x[7]);
    }
}

// ---------------- kernel 4: per-src edge counts ----------------
__global__ void cnt_kernel(const int* __restrict__ src) {
    int i = blockIdx.x * blockDim.x + threadIdx.x;
    if (i < N_EDGES) atomicAdd(&g_cnt[src[i]], 1.0f);
}

// ---------------- kernel 5: fused edge MLP + scatter ----------------
// per block: 128 edges.  GEMM1: ef@Wc (+P gather +bias, silu) -> sM1
// GEMM2: sM1@W2 (+bias, silu) -> vector red into g_msum[src]
__global__ __launch_bounds__(512, 1)
void edge_kernel(const float* __restrict__ ef,
                 const float* __restrict__ msg_w1, const float* __restrict__ b1,
                 const float* __restrict__ msg_w2, const float* __restrict__ b2,
                 const int* __restrict__ src, const int* __restrict__ dst) {
    extern __shared__ float smem[];
    float* sW  = smem;              // Wc, 16384 floats
    float* sW2 = sW + 16384;        // W2, 16384 floats
    float* sA  = sW2 + 16384;       // 16*132
    float* sM1 = sA + 16 * 132;     // 128*132
    int* sSrc  = reinterpret_cast<int*>(sM1 + 128 * 132);
    int* sDst  = sSrc + 128;

    const int tid = threadIdx.x;
    const int rg = tid >> 4;        // 0..31 (4 rows each)
    const int cg = tid & 15;        // 0..15 (8 cols each)
    const int e0 = blockIdx.x * 128;

    const float4* wc4 = reinterpret_cast<const float4*>(msg_w1 + 256 * 128);
    const float4* w24 = reinterpret_cast<const float4*>(msg_w2);
#pragma unroll
    for (int i = 0; i < 8; ++i) {
        reinterpret_cast<float4*>(sW)[tid + i * 512]  = wc4[tid + i * 512];
        reinterpret_cast<float4*>(sW2)[tid + i * 512] = w24[tid + i * 512];
    }
    if (tid < 128) { sSrc[tid] = src[e0 + tid]; sDst[tid] = dst[e0 + tid]; }

    unsigned long long acc[4][4];
#pragma unroll
    for (int r = 0; r < 4; ++r)
#pragma unroll
        for (int p = 0; p < 4; ++p) acc[r][p] = 0ull;

    const int arow = tid >> 2;
    const int akk  = (tid & 3) * 4;

    // GEMM1: t = ef @ Wc
    for (int kc = 0; kc < 8; ++kc) {
        if (kc) __syncthreads();
        float4 v = *reinterpret_cast<const float4*>(
            ef + (size_t)(e0 + arow) * 128 + kc * 16 + akk);
        sA[(akk + 0) * 132 + arow] = v.x;
        sA[(akk + 1) * 132 + arow] = v.y;
        sA[(akk + 2) * 132 + arow] = v.z;
        sA[(akk + 3) * 132 + arow] = v.w;
        __syncthreads();
        mma16(sA, sW + kc * 16 * 128, rg, cg, acc);
    }

    // epilogue 1: + Pa[src] + Pb[dst] + b1, silu -> sM1[row][k]
    float bias[8];
#pragma unroll
    for (int c = 0; c < 8; ++c) bias[c] = b1[cg * 8 + c];

#pragma unroll
    for (int r = 0; r < 4; ++r) {
        int row = rg * 4 + r;
        int s = sSrc[row], d = sDst[row];
        const float* pa = g_P + (size_t)s * 256 + cg * 8;
        const float* pb = g_P + (size_t)d * 256 + 128 + cg * 8;
        float4 pa0 = *reinterpret_cast<const float4*>(pa);
        float4 pa1 = *reinterpret_cast<const float4*>(pa + 4);
        float4 pb0 = *reinterpret_cast<const float4*>(pb);
        float4 pb1 = *reinterpret_cast<const float4*>(pb + 4);
        float x[8];
        unpack_acc8(acc[r], x);
        x[0] += bias[0] + pa0.x + pb0.x;
        x[1] += bias[1] + pa0.y + pb0.y;
        x[2] += bias[2] + pa0.z + pb0.z;
        x[3] += bias[3] + pa0.w + pb0.w;
        x[4] += bias[4] + pa1.x + pb1.x;
        x[5] += bias[5] + pa1.y + pb1.y;
        x[6] += bias[6] + pa1.z + pb1.z;
        x[7] += bias[7] + pa1.w + pb1.w;
        float* m = sM1 + row * 132 + cg * 8;
        *reinterpret_cast<float4*>(m) =
            make_float4(silu_f(x[0]), silu_f(x[1]), silu_f(x[2]), silu_f(x[3]));
        *reinterpret_cast<float4*>(m + 4) =
            make_float4(silu_f(x[4]), silu_f(x[5]), silu_f(x[6]), silu_f(x[7]));
    }
    __syncthreads();

    // GEMM2: m = silu(m1 @ W2 + b2), scatter into g_msum[src]
#pragma unroll
    for (int r = 0; r < 4; ++r)
#pragma unroll
        for (int p = 0; p < 4; ++p) acc[r][p] = 0ull;

    gemm2_128(sM1, sW2, rg, cg, acc);

#pragma unroll
    for (int c = 0; c < 8; ++c) bias[c] = b2[cg * 8 + c];

#pragma unroll
    for (int r = 0; r < 4; ++r) {
        int row = rg * 4 + r;
        int s = sSrc[row];
        float x[8];
        unpack_acc8(acc[r], x);
#pragma unroll
        for (int c = 0; c < 8; ++c) x[c] = silu_f(x[c] + bias[c]);
        float* outp = g_msum + (size_t)s * 128 + cg * 8;
        red_add4(outp,     x[0], x[1], x[2], x[3]);
        red_add4(outp + 4, x[4], x[5], x[6], x[7]);
    }
}

// ---------------- kernel 6: aggregation MLP + residual ----------------
__global__ __launch_bounds__(512, 1)
void agg_kernel(const float* __restrict__ nf,
                const float* __restrict__ agg_w1, const float* __restrict__ ab1,
                const float* __restrict__ agg_w2, const float* __restrict__ ab2,
                float* __restrict__ out) {
    extern __shared__ float smem[];
    float* sW  = smem;            // 16384 floats, reused 3x
    float* sA  = sW + 16384;      // 16*132
    float* sM1 = sA + 16 * 132;   // 128*132

    const int tid = threadIdx.x;
    const int rg = tid >> 4;
    const int cg = tid & 15;
    const int n0 = blockIdx.x * 128;
    const int arow = tid >> 2;
    const int akk  = (tid & 3) * 4;

    unsigned long long acc[4][4];
#pragma unroll
    for (int r = 0; r < 4; ++r)
#pragma unroll
        for (int p = 0; p < 4; ++p) acc[r][p] = 0ull;

    // ---- phase 1: A = h, W = agg_w1 rows [0,128) ----
    {
        const float4* w4 = reinterpret_cast<const float4*>(agg_w1);
#pragma unroll
        for (int i = 0; i < 8; ++i)
            reinterpret_cast<float4*>(sW)[tid + i * 512] = w4[tid + i * 512];
        for (int kc = 0; kc < 8; ++kc) {
            if (kc) __syncthreads();
            int n = n0 + arow;
            float4 v = make_float4(0.f, 0.f, 0.f, 0.f);
            if (n < N_NODES)
                v = *reinterpret_cast<const float4*>(g_h + (size_t)n * 128 + kc * 16 + akk);
            sA[(akk + 0) * 132 + arow] = v.x;
            sA[(akk + 1) * 132 + arow] = v.y;
            sA[(akk + 2) * 132 + arow] = v.z;
            sA[(akk + 3) * 132 + arow] = v.w;
            __syncthreads();
            mma16(sA, sW + kc * 16 * 128, rg, cg, acc);
        }
    }
    __syncthreads();  // phase-1 reads of sW/sA complete

    // ---- phase 2: A = mean = msum/max(cnt,1), W = agg_w1 rows [128,256) ----
    {
        const float4* w4 = reinterpret_cast<const float4*>(agg_w1 + 128 * 128);
#pragma unroll
        for (int i = 0; i < 8; ++i)
            reinterpret_cast<float4*>(sW)[tid + i * 512] = w4[tid + i * 512];
        for (int kc = 0; kc < 8; ++kc) {
            if (kc) __syncthreads();
            int n = n0 + arow;
            float4 v = make_float4(0.f, 0.f, 0.f, 0.f);
            if (n < N_NODES) {
                v = *reinterpret_cast<const float4*>(g_msum + (size_t)n * 128 + kc * 16 + akk);
                float inv = 1.0f / fmaxf(g_cnt[n], 1.0f);
                v.x *= inv; v.y *= inv; v.z *= inv; v.w *= inv;
            }
            sA[(akk + 0) * 132 + arow] = v.x;
            sA[(akk + 1) * 132 + arow] = v.y;
            sA[(akk + 2) * 132 + arow] = v.z;
            sA[(akk + 3) * 132 + arow] = v.w;
            __syncthreads();
            mma16(sA, sW + kc * 16 * 128, rg, cg, acc);
        }
    }

    // epilogue 1: silu(acc + ab1) -> sM1[row][k]
    float bias[8];
#pragma unroll
    for (int c = 0; c < 8; ++c) bias[c] = ab1[cg * 8 + c];
#pragma unroll
    for (int r = 0; r < 4; ++r) {
        int row = rg * 4 + r;
        float x[8];
        unpack_acc8(acc[r], x);
        float* m = sM1 + row * 132 + cg * 8;
        *reinterpret_cast<float4*>(m) = make_float4(
            silu_f(x[0] + bias[0]), silu_f(x[1] + bias[1]),
            silu_f(x[2] + bias[2]), silu_f(x[3] + bias[3]));
        *reinterpret_cast<float4*>(m + 4) = make_float4(
            silu_f(x[4] + bias[4]), silu_f(x[5] + bias[5]),
            silu_f(x[6] + bias[6]), silu_f(x[7] + bias[7]));
    }
    __syncthreads();  // phase-2 sW reads + sM1 writes complete

    // load agg_w2
    {
        const float4* w4 = reinterpret_cast<const float4*>(agg_w2);
#pragma unroll
        for (int i = 0; i < 8; ++i)
            reinterpret_cast<float4*>(sW)[tid + i * 512] = w4[tid + i * 512];
    }
    __syncthreads();

#pragma unroll
    for (int r = 0; r < 4; ++r)
#pragma unroll
        for (int p = 0; p < 4; ++p) acc[r][p] = 0ull;

    gemm2_128(sM1, sW, rg, cg, acc);

    // epilogue: out = node_features + silu(acc + ab2)
#pragma unroll
    for (int c = 0; c < 8; ++c) bias[c] = ab2[cg * 8 + c];
#pragma unroll
    for (int r = 0; r < 4; ++r) {
        int n = n0 + rg * 4 + r;
        if (n >= N_NODES) continue;
        float x[8];
        unpack_acc8(acc[r], x);
        const float* nfp = nf + (size_t)n * 128 + cg * 8;
        float4 f0 = *reinterpret_cast<const float4*>(nfp);
        float4 f1 = *reinterpret_cast<const float4*>(nfp + 4);
        float* o = out + (size_t)n * 128 + cg * 8;
        *reinterpret_cast<float4*>(o) = make_float4(
            f0.x + silu_f(x[0] + bias[0]), f0.y + silu_f(x[1] + bias[1]),
            f0.z + silu_f(x[2] + bias[2]), f0.w + silu_f(x[3] + bias[3]));
        *reinterpret_cast<float4*>(o + 4) = make_float4(
            f1.x + silu_f(x[4] + bias[4]), f1.y + silu_f(x[5] + bias[5]),
            f1.z + silu_f(x[6] + bias[6]), f1.w + silu_f(x[7] + bias[7]));
    }
}

// ---------------- launcher ----------------
extern "C" void kernel_launch(void* const* d_in, const int* in_sizes, int n_in,
                              void* d_out, int out_size) {
    (void)in_sizes; (void)n_in; (void)out_size;
    const float* nf  = (const float*)d_in[0];
    const float* ef  = (const float*)d_in[1];
    const float* gam = (const float*)d_in[2];
    const float* bet = (const float*)d_in[3];
    const float* mw1 = (const float*)d_in[4];
    const float* mb1 = (const float*)d_in[5];
    const float* mw2 = (const float*)d_in[6];
    const float* mb2 = (const float*)d_in[7];
    const float* aw1 = (const float*)d_in[8];
    const float* ab1 = (const float*)d_in[9];
    const float* aw2 = (const float*)d_in[10];
    const float* ab2 = (const float*)d_in[11];
    const int* eidx  = (const int*)d_in[12];
    const int* src = eidx;
    const int* dst = eidx + N_EDGES;
    float* out = (float*)d_out;

    const int EDGE_SMEM = (16384 + 16384 + 16 * 132 + 128 * 132) * 4 + 256 * 4;
    const int AGG_SMEM  = (16384 + 16 * 132 + 128 * 132) * 4;
    const int P_SMEM    = (16384 + 16 * 132) * 4;

    cudaFuncSetAttribute(edge_kernel,  cudaFuncAttributeMaxDynamicSharedMemorySize, EDGE_SMEM);
    cudaFuncSetAttribute(agg_kernel,   cudaFuncAttributeMaxDynamicSharedMemorySize, AGG_SMEM);
    cudaFuncSetAttribute(pnode_kernel, cudaFuncAttributeMaxDynamicSharedMemorySize, P_SMEM);

    const int NODE_TILES = (N_NODES + 127) / 128;  // 313

    zero_kernel<<<(N_NODES * D / 4 + 255) / 256, 256>>>();
    ln_kernel<<<N_NODES / 8, 256>>>(nf, gam, bet);
    pnode_kernel<<<dim3(NODE_TILES, 2), 512, P_SMEM>>>(mw1);
    cnt_kernel<<<(N_EDGES + 255) / 256, 256>>>(src);
    edge_kernel<<<N_EDGES / 128, 512, EDGE_SMEM>>>(ef, mw1, mb1, mw2, mb2, src, dst);
    agg_kernel<<<NODE_TILES, 512, AGG_SMEM>>>(nf, aw1, ab1, aw2, ab2, out);
}

// round 3
// speedup vs baseline: 1.2984x; 1.2984x over previous
#include <cuda_runtime.h>
#include <cuda_fp16.h>
#include <mma.h>
#include <cstdint>

using namespace nvcuda;

// Problem constants
#define N_NODES 40000
#define N_EDGES 640000
#define D 128

// tile strides
#define KP 136           // half elements per row in A/W tiles (pad 8)
#define SP 132           // float elements per row in staging

// ---------------- device scratch ----------------
__device__ float g_h[N_NODES * D];
__device__ float g_P[N_NODES * 2 * D];
__device__ float g_msum[N_NODES * D];
__device__ float g_cnt[N_NODES];

// Pre-split fp16 weights, layout [n][KP] (B col-major for wmma), hi/lo parts.
__device__ __align__(32) half g_WcHi[128 * KP];
__device__ __align__(32) half g_WcLo[128 * KP];
__device__ __align__(32) half g_W2Hi[128 * KP];
__device__ __align__(32) half g_W2Lo[128 * KP];

// ---------------- generic helpers ----------------
__device__ __forceinline__ float silu_f(float x) {
    return x / (1.0f + __expf(-x));
}

__device__ __forceinline__ unsigned long long pack2(float x, float y) {
    unsigned long long r;
    asm("mov.b64 %0, {%1, %2};" : "=l"(r) : "f"(x), "f"(y));
    return r;
}

__device__ __forceinline__ void fma2(unsigned long long &d,
                                     unsigned long long a,
                                     unsigned long long b) {
    asm("fma.rn.f32x2 %0, %1, %2, %0;" : "+l"(d) : "l"(a), "l"(b));
}

__device__ __forceinline__ float2 unpack2(unsigned long long v) {
    float lo, hi;
    asm("mov.b64 {%0, %1}, %2;" : "=f"(lo), "=f"(hi) : "l"(v));
    return make_float2(lo, hi);
}

__device__ __forceinline__ void unpack_acc8(const unsigned long long a[4], float x[8]) {
    float2 t;
    t = unpack2(a[0]); x[0] = t.x; x[1] = t.y;
    t = unpack2(a[1]); x[2] = t.x; x[3] = t.y;
    t = unpack2(a[2]); x[4] = t.x; x[5] = t.y;
    t = unpack2(a[3]); x[6] = t.x; x[7] = t.y;
}

__device__ __forceinline__ void red_add4(float* p, float a, float b, float c, float d) {
    asm volatile("red.global.add.v4.f32 [%0], {%1, %2, %3, %4};"
                 :: "l"(p), "f"(a), "f"(b), "f"(c), "f"(d) : "memory");
}

__device__ __forceinline__ void split_h(float x, half &h, half &l) {
    h = __float2half_rn(x);
    l = __float2half_rn(x - __half2float(h));
}

__device__ __forceinline__ uint32_t pack_h2(half a, half b) {
    __half2 t = __halves2half2(a, b);
    return *reinterpret_cast<uint32_t*>(&t);
}

// ---------------- fp32 SIMT micro-GEMM (pnode/agg) ----------------
__device__ __forceinline__ void mma16(const float* __restrict__ sA,
                                      const float* __restrict__ sWk,
                                      int rg, int cg,
                                      unsigned long long acc[4][4]) {
#pragma unroll
    for (int k = 0; k < 16; ++k) {
        float4 a4 = *reinterpret_cast<const float4*>(sA + k * 132 + rg * 4);
        const float* wr = sWk + k * 128 + cg * 8;
        ulonglong2 b01 = *reinterpret_cast<const ulonglong2*>(wr);
        ulonglong2 b23 = *reinterpret_cast<const ulonglong2*>(wr + 4);
        float a[4] = {a4.x, a4.y, a4.z, a4.w};
#pragma unroll
        for (int r = 0; r < 4; ++r) {
            unsigned long long ap = pack2(a[r], a[r]);
            fma2(acc[r][0], ap, b01.x);
            fma2(acc[r][1], ap, b01.y);
            fma2(acc[r][2], ap, b23.x);
            fma2(acc[r][3], ap, b23.y);
        }
    }
}

__device__ __forceinline__ void gemm2_128(const float* __restrict__ sM1,
                                          const float* __restrict__ sW2,
                                          int rg, int cg,
                                          unsigned long long acc[4][4]) {
    const int r0 = rg * 4;
#pragma unroll 8
    for (int k = 0; k < 128; ++k) {
        const float* wr = sW2 + k * 128 + cg * 8;
        ulonglong2 b01 = *reinterpret_cast<const ulonglong2*>(wr);
        ulonglong2 b23 = *reinterpret_cast<const ulonglong2*>(wr + 4);
#pragma unroll
        for (int r = 0; r < 4; ++r) {
            float a = sM1[(r0 + r) * 132 + k];
            unsigned long long ap = pack2(a, a);
            fma2(acc[r][0], ap, b01.x);
            fma2(acc[r][1], ap, b01.y);
            fma2(acc[r][2], ap, b23.x);
            fma2(acc[r][3], ap, b23.y);
        }
    }
}

// ---------------- kernel: zero scratch ----------------
__global__ void zero_kernel() {
    int i = blockIdx.x * blockDim.x + threadIdx.x;
    const int total4 = N_NODES * D / 4;
    if (i < total4) reinterpret_cast<float4*>(g_msum)[i] = make_float4(0.f, 0.f, 0.f, 0.f);
    if (i < N_NODES) g_cnt[i] = 0.0f;
}

// ---------------- kernel: LayerNorm ----------------
__global__ void ln_kernel(const float* __restrict__ x,
                          const float* __restrict__ gamma,
                          const float* __restrict__ beta) {
    int warp = threadIdx.x >> 5;
    int lane = threadIdx.x & 31;
    int n = blockIdx.x * 8 + warp;
    float4 v = *reinterpret_cast<const float4*>(x + (size_t)n * D + lane * 4);
    float s = v.x + v.y + v.z + v.w;
#pragma unroll
    for (int o = 16; o > 0; o >>= 1) s += __shfl_xor_sync(0xffffffffu, s, o);
    float mu = s * (1.0f / D);
    float d0 = v.x - mu, d1 = v.y - mu, d2 = v.z - mu, d3 = v.w - mu;
    float ss = d0 * d0 + d1 * d1 + d2 * d2 + d3 * d3;
#pragma unroll
    for (int o = 16; o > 0; o >>= 1) ss += __shfl_xor_sync(0xffffffffu, ss, o);
    float rs = rsqrtf(ss * (1.0f / D) + 1e-5f);
    float4 g = *reinterpret_cast<const float4*>(gamma + lane * 4);
    float4 b = *reinterpret_cast<const float4*>(beta + lane * 4);
    float4 o4;
    o4.x = d0 * rs * g.x + b.x;
    o4.y = d1 * rs * g.y + b.y;
    o4.z = d2 * rs * g.z + b.z;
    o4.w = d3 * rs * g.w + b.w;
    *reinterpret_cast<float4*>(g_h + (size_t)n * D + lane * 4) = o4;
}

// ---------------- kernel: node projections P = h @ [Wa | Wb] ----------------
__global__ __launch_bounds__(512, 1)
void pnode_kernel(const float* __restrict__ msg_w1) {
    extern __shared__ float smem[];
    float* sW = smem;
    float* sA = sW + 16384;

    const int tid = threadIdx.x;
    const int rg = tid >> 4;
    const int cg = tid & 15;
    const int n0 = blockIdx.x * 128;
    const int half_ = blockIdx.y;

    const float4* w4 = reinterpret_cast<const float4*>(msg_w1 + half_ * 128 * 128);
#pragma unroll
    for (int i = 0; i < 8; ++i)
        reinterpret_cast<float4*>(sW)[tid + i * 512] = w4[tid + i * 512];

    unsigned long long acc[4][4];
#pragma unroll
    for (int r = 0; r < 4; ++r)
#pragma unroll
        for (int p = 0; p < 4; ++p) acc[r][p] = 0ull;

    const int arow = tid >> 2;
    const int akk  = (tid & 3) * 4;

    for (int kc = 0; kc < 8; ++kc) {
        if (kc) __syncthreads();
        int n = n0 + arow;
        float4 v = make_float4(0.f, 0.f, 0.f, 0.f);
        if (n < N_NODES)
            v = *reinterpret_cast<const float4*>(g_h + (size_t)n * 128 + kc * 16 + akk);
        sA[(akk + 0) * 132 + arow] = v.x;
        sA[(akk + 1) * 132 + arow] = v.y;
        sA[(akk + 2) * 132 + arow] = v.z;
        sA[(akk + 3) * 132 + arow] = v.w;
        __syncthreads();
        mma16(sA, sW + kc * 16 * 128, rg, cg, acc);
    }

#pragma unroll
    for (int r = 0; r < 4; ++r) {
        int n = n0 + rg * 4 + r;
        if (n >= N_NODES) continue;
        float x[8];
        unpack_acc8(acc[r], x);
        float* dst = g_P + (size_t)n * 256 + half_ * 128 + cg * 8;
        *reinterpret_cast<float4*>(dst)     = make_float4(x[0], x[1], x[2], x[3]);
        *reinterpret_cast<float4*>(dst + 4) = make_float4(x[4], x[5], x[6], x[7]);
    }
}

// ---------------- kernel: per-src edge counts ----------------
__global__ void cnt_kernel(const int* __restrict__ src) {
    int i = blockIdx.x * blockDim.x + threadIdx.x;
    if (i < N_EDGES) atomicAdd(&g_cnt[src[i]], 1.0f);
}

// ---------------- kernel: pre-split weights to fp16 hi/lo, [n][KP] ----------
__global__ void wprep_kernel(const float* __restrict__ mw1,
                             const float* __restrict__ mw2) {
    int i = blockIdx.x * blockDim.x + threadIdx.x;
    if (i >= 32768) return;
    int mat = i >> 14;
    int r = i & 16383;
    int n = r >> 7;
    int k = r & 127;
    float v = (mat == 0) ? mw1[(256 + k) * 128 + n] : mw2[k * 128 + n];
    half h, l;
    split_h(v, h, l);
    int off = n * KP + k;
    if (mat == 0) { g_WcHi[off] = h; g_WcLo[off] = l; }
    else          { g_W2Hi[off] = h; g_W2Lo[off] = l; }
}

// ---------------- fused edge MLP + scatter (wmma fp16 3-split) --------------
// smem layout (bytes from aligned base):
#define SM_AHI   0                       // 34816
#define SM_ALO   34816
#define SM_WCHI  69632                   // staging (128x132 f32 = 67584) aliases WCHI+WCLO
#define SM_WCLO  104448
#define SM_W2HI  139264
#define SM_W2LO  174080
#define SM_AUX   208896                  // sSrc 512 | sDst 512 | sB1 512 | sB2 512
#define EDGE_SMEM_W (208896 + 2048 + 1024)

// one wmma GEMM pass: D(staging fp32) = Ahi*Bhi + Alo*Bhi + Ahi*Blo
__device__ __forceinline__ void wmma_gemm3(const half* __restrict__ aHi,
                                           const half* __restrict__ aLo,
                                           const half* __restrict__ bHi,
                                           const half* __restrict__ bLo,
                                           float* __restrict__ staging,
                                           int wm, int wn) {
    wmma::fragment<wmma::accumulator, 16, 16, 16, float> c[2][4];
#pragma unroll
    for (int i = 0; i < 2; ++i)
#pragma unroll
        for (int j = 0; j < 4; ++j) wmma::fill_fragment(c[i][j], 0.0f);

#pragma unroll
    for (int ks = 0; ks < 8; ++ks) {
        const int k0 = ks * 16;
        wmma::fragment<wmma::matrix_a, 16, 16, 16, half, wmma::row_major> ah[2], al[2];
#pragma unroll
        for (int i = 0; i < 2; ++i) {
            const int m0 = wm * 32 + i * 16;
            wmma::load_matrix_sync(ah[i], aHi + m0 * KP + k0, KP);
            wmma::load_matrix_sync(al[i], aLo + m0 * KP + k0, KP);
        }
#pragma unroll
        for (int j = 0; j < 4; ++j) {
            const int n0 = wn * 64 + j * 16;
            wmma::fragment<wmma::matrix_b, 16, 16, 16, half, wmma::col_major> bh, bl;
            wmma::load_matrix_sync(bh, bHi + n0 * KP + k0, KP);
            wmma::load_matrix_sync(bl, bLo + n0 * KP + k0, KP);
#pragma unroll
            for (int i = 0; i < 2; ++i) {
                wmma::mma_sync(c[i][j], ah[i], bh, c[i][j]);
                wmma::mma_sync(c[i][j], al[i], bh, c[i][j]);
                wmma::mma_sync(c[i][j], ah[i], bl, c[i][j]);
            }
        }
    }
    __syncthreads();   // everyone done reading B (staging aliases Wc on pass 1)
#pragma unroll
    for (int i = 0; i < 2; ++i)
#pragma unroll
        for (int j = 0; j < 4; ++j)
            wmma::store_matrix_sync(staging + (wm * 32 + i * 16) * SP + wn * 64 + j * 16,
                                    c[i][j], SP, wmma::mem_row_major);
    __syncthreads();
}

__global__ __launch_bounds__(256, 1)
void edge_wmma_kernel(const float* __restrict__ ef,
                      const float* __restrict__ b1, const float* __restrict__ b2,
                      const int* __restrict__ src, const int* __restrict__ dst) {
    extern __shared__ char smraw[];
    char* base = (char*)(((uintptr_t)smraw + 1023) & ~(uintptr_t)1023);

    half* sAHi = (half*)(base + SM_AHI);
    half* sALo = (half*)(base + SM_ALO);
    half* sWcHi = (half*)(base + SM_WCHI);
    half* sWcLo = (half*)(base + SM_WCLO);
    half* sW2Hi = (half*)(base + SM_W2HI);
    half* sW2Lo = (half*)(base + SM_W2LO);
    float* staging = (float*)(base + SM_WCHI);   // aliases Wc after GEMM1
    int*   sSrc = (int*)(base + SM_AUX + 0);
    int*   sDst = (int*)(base + SM_AUX + 512);
    float* sB1  = (float*)(base + SM_AUX + 1024);
    float* sB2  = (float*)(base + SM_AUX + 1536);

    const int tid = threadIdx.x;
    const int wid = tid >> 5;
    const int wm = wid & 3;      // row group (32 rows)
    const int wn = wid >> 2;     // col group (64 cols)
    const int e0 = blockIdx.x * 128;

    // ---- cooperative loads: weights (linear), edge ids, biases ----
    {
        const uint4* gw[4] = {(const uint4*)g_WcHi, (const uint4*)g_WcLo,
                              (const uint4*)g_W2Hi, (const uint4*)g_W2Lo};
        uint4* sw[4] = {(uint4*)sWcHi, (uint4*)sWcLo, (uint4*)sW2Hi, (uint4*)sW2Lo};
        // 128*KP halves = 34816B = 2176 uint4 per tile
#pragma unroll
        for (int m = 0; m < 4; ++m) {
            for (int idx = tid; idx < 2176; idx += 256)
                sw[m][idx] = gw[m][idx];
        }
    }
    if (tid < 128) {
        sSrc[tid] = src[e0 + tid];
        sDst[tid] = dst[e0 + tid];
        sB1[tid] = b1[tid];
        sB2[tid] = b2[tid];
    }

    // ---- A tile: ef rows split to fp16 hi/lo ----
    {
        const int row = tid >> 1;
        const int c0 = (tid & 1) * 64;
        const float4* srcp = (const float4*)(ef + (size_t)(e0 + row) * 128 + c0);
        half* dh = sAHi + row * KP + c0;
        half* dl = sALo + row * KP + c0;
#pragma unroll
        for (int g = 0; g < 16; ++g) {
            float4 v = srcp[g];
            half h0, l0, h1, l1, h2, l2, h3, l3;
            split_h(v.x, h0, l0); split_h(v.y, h1, l1);
            split_h(v.z, h2, l2); split_h(v.w, h3, l3);
            uint2 hp = make_uint2(pack_h2(h0, h1), pack_h2(h2, h3));
            uint2 lp = make_uint2(pack_h2(l0, l1), pack_h2(l2, l3));
            *(uint2*)(dh + g * 4) = hp;
            *(uint2*)(dl + g * 4) = lp;
        }
    }
    __syncthreads();

    // ---- GEMM1: staging = ef @ Wc (3-split) ----
    wmma_gemm3(sAHi, sALo, sWcHi, sWcLo, staging, wm, wn);

    // ---- epilogue 1: m1 = silu(staging + Pa[src] + Pb[dst] + b1) -> A tiles ----
    {
        const int row = tid >> 1;
        const int c0 = (tid & 1) * 64;
        const int s = sSrc[row], dn = sDst[row];
        const float* pa = g_P + (size_t)s * 256 + c0;
        const float* pb = g_P + (size_t)dn * 256 + 128 + c0;
        const float* st = staging + row * SP + c0;
        half* dh = sAHi + row * KP + c0;
        half* dl = sALo + row * KP + c0;
#pragma unroll
        for (int g = 0; g < 16; ++g) {
            float4 d4 = *(const float4*)(st + g * 4);
            float4 A = *(const float4*)(pa + g * 4);
            float4 B = *(const float4*)(pb + g * 4);
            int c = c0 + g * 4;
            float x0 = silu_f(d4.x + A.x + B.x + sB1[c + 0]);
            float x1 = silu_f(d4.y + A.y + B.y + sB1[c + 1]);
            float x2 = silu_f(d4.z + A.z + B.z + sB1[c + 2]);
            float x3 = silu_f(d4.w + A.w + B.w + sB1[c + 3]);
            half h0, l0, h1, l1, h2, l2, h3, l3;
            split_h(x0, h0, l0); split_h(x1, h1, l1);
            split_h(x2, h2, l2); split_h(x3, h3, l3);
            *(uint2*)(dh + g * 4) = make_uint2(pack_h2(h0, h1), pack_h2(h2, h3));
            *(uint2*)(dl + g * 4) = make_uint2(pack_h2(l0, l1), pack_h2(l2, l3));
        }
    }
    __syncthreads();

    // ---- GEMM2: staging = m1 @ W2 (3-split) ----
    wmma_gemm3(sAHi, sALo, sW2Hi, sW2Lo, staging, wm, wn);

    // ---- epilogue 2: msg = silu(staging + b2) -> scatter-add g_msum[src] ----
    {
        const int row = tid >> 1;
        const int c0 = (tid & 1) * 64;
        const int s = sSrc[row];
        const float* st = staging + row * SP + c0;
        float* outp = g_msum + (size_t)s * 128 + c0;
#pragma unroll
        for (int g = 0; g < 16; ++g) {
            float4 d4 = *(const float4*)(st + g * 4);
            int c = c0 + g * 4;
            red_add4(outp + g * 4,
                     silu_f(d4.x + sB2[c + 0]), silu_f(d4.y + sB2[c + 1]),
                     silu_f(d4.z + sB2[c + 2]), silu_f(d4.w + sB2[c + 3]));
        }
    }
}

// ---------------- kernel: aggregation MLP + residual ----------------
__global__ __launch_bounds__(512, 1)
void agg_kernel(const float* __restrict__ nf,
                const float* __restrict__ agg_w1, const float* __restrict__ ab1,
                const float* __restrict__ agg_w2, const float* __restrict__ ab2,
                float* __restrict__ out) {
    extern __shared__ float smem[];
    float* sW  = smem;
    float* sA  = sW + 16384;
    float* sM1 = sA + 16 * 132;

    const int tid = threadIdx.x;
    const int rg = tid >> 4;
    const int cg = tid & 15;
    const int n0 = blockIdx.x * 128;
    const int arow = tid >> 2;
    const int akk  = (tid & 3) * 4;

    unsigned long long acc[4][4];
#pragma unroll
    for (int r = 0; r < 4; ++r)
#pragma unroll
        for (int p = 0; p < 4; ++p) acc[r][p] = 0ull;

    {
        const float4* w4 = reinterpret_cast<const float4*>(agg_w1);
#pragma unroll
        for (int i = 0; i < 8; ++i)
            reinterpret_cast<float4*>(sW)[tid + i * 512] = w4[tid + i * 512];
        for (int kc = 0; kc < 8; ++kc) {
            if (kc) __syncthreads();
            int n = n0 + arow;
            float4 v = make_float4(0.f, 0.f, 0.f, 0.f);
            if (n < N_NODES)
                v = *reinterpret_cast<const float4*>(g_h + (size_t)n * 128 + kc * 16 + akk);
            sA[(akk + 0) * 132 + arow] = v.x;
            sA[(akk + 1) * 132 + arow] = v.y;
            sA[(akk + 2) * 132 + arow] = v.z;
            sA[(akk + 3) * 132 + arow] = v.w;
            __syncthreads();
            mma16(sA, sW + kc * 16 * 128, rg, cg, acc);
        }
    }
    __syncthreads();

    {
        const float4* w4 = reinterpret_cast<const float4*>(agg_w1 + 128 * 128);
#pragma unroll
        for (int i = 0; i < 8; ++i)
            reinterpret_cast<float4*>(sW)[tid + i * 512] = w4[tid + i * 512];
        for (int kc = 0; kc < 8; ++kc) {
            if (kc) __syncthreads();
            int n = n0 + arow;
            float4 v = make_float4(0.f, 0.f, 0.f, 0.f);
            if (n < N_NODES) {
                v = *reinterpret_cast<const float4*>(g_msum + (size_t)n * 128 + kc * 16 + akk);
                float inv = 1.0f / fmaxf(g_cnt[n], 1.0f);
                v.x *= inv; v.y *= inv; v.z *= inv; v.w *= inv;
            }
            sA[(akk + 0) * 132 + arow] = v.x;
            sA[(akk + 1) * 132 + arow] = v.y;
            sA[(akk + 2) * 132 + arow] = v.z;
            sA[(akk + 3) * 132 + arow] = v.w;
            __syncthreads();
            mma16(sA, sW + kc * 16 * 128, rg, cg, acc);
        }
    }

    float bias[8];
#pragma unroll
    for (int c = 0; c < 8; ++c) bias[c] = ab1[cg * 8 + c];
#pragma unroll
    for (int r = 0; r < 4; ++r) {
        int row = rg * 4 + r;
        float x[8];
        unpack_acc8(acc[r], x);
        float* m = sM1 + row * 132 + cg * 8;
        *reinterpret_cast<float4*>(m) = make_float4(
            silu_f(x[0] + bias[0]), silu_f(x[1] + bias[1]),
            silu_f(x[2] + bias[2]), silu_f(x[3] + bias[3]));
        *reinterpret_cast<float4*>(m + 4) = make_float4(
            silu_f(x[4] + bias[4]), silu_f(x[5] + bias[5]),
            silu_f(x[6] + bias[6]), silu_f(x[7] + bias[7]));
    }
    __syncthreads();

    {
        const float4* w4 = reinterpret_cast<const float4*>(agg_w2);
#pragma unroll
        for (int i = 0; i < 8; ++i)
            reinterpret_cast<float4*>(sW)[tid + i * 512] = w4[tid + i * 512];
    }
    __syncthreads();

#pragma unroll
    for (int r = 0; r < 4; ++r)
#pragma unroll
        for (int p = 0; p < 4; ++p) acc[r][p] = 0ull;

    gemm2_128(sM1, sW, rg, cg, acc);

#pragma unroll
    for (int c = 0; c < 8; ++c) bias[c] = ab2[cg * 8 + c];
#pragma unroll
    for (int r = 0; r < 4; ++r) {
        int n = n0 + rg * 4 + r;
        if (n >= N_NODES) continue;
        float x[8];
        unpack_acc8(acc[r], x);
        const float* nfp = nf + (size_t)n * 128 + cg * 8;
        float4 f0 = *reinterpret_cast<const float4*>(nfp);
        float4 f1 = *reinterpret_cast<const float4*>(nfp + 4);
        float* o = out + (size_t)n * 128 + cg * 8;
        *reinterpret_cast<float4*>(o) = make_float4(
            f0.x + silu_f(x[0] + bias[0]), f0.y + silu_f(x[1] + bias[1]),
            f0.z + silu_f(x[2] + bias[2]), f0.w + silu_f(x[3] + bias[3]));
        *reinterpret_cast<float4*>(o + 4) = make_float4(
            f1.x + silu_f(x[4] + bias[4]), f1.y + silu_f(x[5] + bias[5]),
            f1.z + silu_f(x[6] + bias[6]), f1.w + silu_f(x[7] + bias[7]));
    }
}

// ---------------- launcher ----------------
extern "C" void kernel_launch(void* const* d_in, const int* in_sizes, int n_in,
                              void* d_out, int out_size) {
    (void)in_sizes; (void)n_in; (void)out_size;
    const float* nf  = (const float*)d_in[0];
    const float* ef  = (const float*)d_in[1];
    const float* gam = (const float*)d_in[2];
    const float* bet = (const float*)d_in[3];
    const float* mw1 = (const float*)d_in[4];
    const float* mb1 = (const float*)d_in[5];
    const float* mw2 = (const float*)d_in[6];
    const float* mb2 = (const float*)d_in[7];
    const float* aw1 = (const float*)d_in[8];
    const float* ab1 = (const float*)d_in[9];
    const float* aw2 = (const float*)d_in[10];
    const float* ab2 = (const float*)d_in[11];
    const int* eidx  = (const int*)d_in[12];
    const int* src = eidx;
    const int* dst = eidx + N_EDGES;
    float* out = (float*)d_out;

    const int AGG_SMEM = (16384 + 16 * 132 + 128 * 132) * 4;
    const int P_SMEM   = (16384 + 16 * 132) * 4;

    cudaFuncSetAttribute(edge_wmma_kernel, cudaFuncAttributeMaxDynamicSharedMemorySize, EDGE_SMEM_W);
    cudaFuncSetAttribute(agg_kernel,   cudaFuncAttributeMaxDynamicSharedMemorySize, AGG_SMEM);
    cudaFuncSetAttribute(pnode_kernel, cudaFuncAttributeMaxDynamicSharedMemorySize, P_SMEM);

    const int NODE_TILES = (N_NODES + 127) / 128;  // 313

    zero_kernel<<<(N_NODES * D / 4 + 255) / 256, 256>>>();
    ln_kernel<<<N_NODES / 8, 256>>>(nf, gam, bet);
    wprep_kernel<<<128, 256>>>(mw1, mw2);
    pnode_kernel<<<dim3(NODE_TILES, 2), 512, P_SMEM>>>(mw1);
    cnt_kernel<<<(N_EDGES + 255) / 256, 256>>>(src);
    edge_wmma_kernel<<<N_EDGES / 128, 256, EDGE_SMEM_W>>>(ef, mb1, mb2, src, dst);
    agg_kernel<<<NODE_TILES, 512, AGG_SMEM>>>(nf, aw1, ab1, aw2, ab2, out);
}

// round 4
// speedup vs baseline: 1.4157x; 1.0904x over previous
#include <cuda_runtime.h>
#include <cuda_fp16.h>
#include <mma.h>
#include <cstdint>

using namespace nvcuda;

// Problem constants
#define N_NODES 40000
#define N_EDGES 640000
#define D 128

// tile strides
#define KP 136           // half elements per row in A/W tiles (pad 8)
#define SP 132           // float elements per row in staging

// ---------------- device scratch ----------------
__device__ float g_h[N_NODES * D];
__device__ float g_P[N_NODES * 2 * D];
__device__ float g_msum[N_NODES * D];
__device__ float g_cnt[N_NODES];

// Pre-split fp16 weights, layout [n][KP] (B col-major for wmma), hi/lo parts.
__device__ __align__(32) half g_WcHi[128 * KP];
__device__ __align__(32) half g_WcLo[128 * KP];
__device__ __align__(32) half g_W2Hi[128 * KP];
__device__ __align__(32) half g_W2Lo[128 * KP];

// ---------------- generic helpers ----------------
__device__ __forceinline__ float silu_f(float x) {
    return x / (1.0f + __expf(-x));
}

__device__ __forceinline__ unsigned long long pack2(float x, float y) {
    unsigned long long r;
    asm("mov.b64 %0, {%1, %2};" : "=l"(r) : "f"(x), "f"(y));
    return r;
}

__device__ __forceinline__ void fma2(unsigned long long &d,
                                     unsigned long long a,
                                     unsigned long long b) {
    asm("fma.rn.f32x2 %0, %1, %2, %0;" : "+l"(d) : "l"(a), "l"(b));
}

__device__ __forceinline__ float2 unpack2(unsigned long long v) {
    float lo, hi;
    asm("mov.b64 {%0, %1}, %2;" : "=f"(lo), "=f"(hi) : "l"(v));
    return make_float2(lo, hi);
}

__device__ __forceinline__ void unpack_acc8(const unsigned long long a[4], float x[8]) {
    float2 t;
    t = unpack2(a[0]); x[0] = t.x; x[1] = t.y;
    t = unpack2(a[1]); x[2] = t.x; x[3] = t.y;
    t = unpack2(a[2]); x[4] = t.x; x[5] = t.y;
    t = unpack2(a[3]); x[6] = t.x; x[7] = t.y;
}

__device__ __forceinline__ void red_add4(float* p, float a, float b, float c, float d) {
    asm volatile("red.global.add.v4.f32 [%0], {%1, %2, %3, %4};"
                 :: "l"(p), "f"(a), "f"(b), "f"(c), "f"(d) : "memory");
}

__device__ __forceinline__ void split_h(float x, half &h, half &l) {
    h = __float2half_rn(x);
    l = __float2half_rn(x - __half2float(h));
}

__device__ __forceinline__ uint32_t pack_h2(half a, half b) {
    __half2 t = __halves2half2(a, b);
    return *reinterpret_cast<uint32_t*>(&t);
}

// ---------------- fp32 SIMT micro-GEMM (pnode/agg) ----------------
__device__ __forceinline__ void mma16(const float* __restrict__ sA,
                                      const float* __restrict__ sWk,
                                      int rg, int cg,
                                      unsigned long long acc[4][4]) {
#pragma unroll
    for (int k = 0; k < 16; ++k) {
        float4 a4 = *reinterpret_cast<const float4*>(sA + k * 132 + rg * 4);
        const float* wr = sWk + k * 128 + cg * 8;
        ulonglong2 b01 = *reinterpret_cast<const ulonglong2*>(wr);
        ulonglong2 b23 = *reinterpret_cast<const ulonglong2*>(wr + 4);
        float a[4] = {a4.x, a4.y, a4.z, a4.w};
#pragma unroll
        for (int r = 0; r < 4; ++r) {
            unsigned long long ap = pack2(a[r], a[r]);
            fma2(acc[r][0], ap, b01.x);
            fma2(acc[r][1], ap, b01.y);
            fma2(acc[r][2], ap, b23.x);
            fma2(acc[r][3], ap, b23.y);
        }
    }
}

__device__ __forceinline__ void gemm2_128(const float* __restrict__ sM1,
                                          const float* __restrict__ sW2,
                                          int rg, int cg,
                                          unsigned long long acc[4][4]) {
    const int r0 = rg * 4;
#pragma unroll 8
    for (int k = 0; k < 128; ++k) {
        const float* wr = sW2 + k * 128 + cg * 8;
        ulonglong2 b01 = *reinterpret_cast<const ulonglong2*>(wr);
        ulonglong2 b23 = *reinterpret_cast<const ulonglong2*>(wr + 4);
#pragma unroll
        for (int r = 0; r < 4; ++r) {
            float a = sM1[(r0 + r) * 132 + k];
            unsigned long long ap = pack2(a, a);
            fma2(acc[r][0], ap, b01.x);
            fma2(acc[r][1], ap, b01.y);
            fma2(acc[r][2], ap, b23.x);
            fma2(acc[r][3], ap, b23.y);
        }
    }
}

// ---------------- kernel: zero scratch ----------------
__global__ void zero_kernel() {
    int i = blockIdx.x * blockDim.x + threadIdx.x;
    const int total4 = N_NODES * D / 4;
    if (i < total4) reinterpret_cast<float4*>(g_msum)[i] = make_float4(0.f, 0.f, 0.f, 0.f);
    if (i < N_NODES) g_cnt[i] = 0.0f;
}

// ---------------- kernel: LayerNorm ----------------
__global__ void ln_kernel(const float* __restrict__ x,
                          const float* __restrict__ gamma,
                          const float* __restrict__ beta) {
    int warp = threadIdx.x >> 5;
    int lane = threadIdx.x & 31;
    int n = blockIdx.x * 8 + warp;
    float4 v = *reinterpret_cast<const float4*>(x + (size_t)n * D + lane * 4);
    float s = v.x + v.y + v.z + v.w;
#pragma unroll
    for (int o = 16; o > 0; o >>= 1) s += __shfl_xor_sync(0xffffffffu, s, o);
    float mu = s * (1.0f / D);
    float d0 = v.x - mu, d1 = v.y - mu, d2 = v.z - mu, d3 = v.w - mu;
    float ss = d0 * d0 + d1 * d1 + d2 * d2 + d3 * d3;
#pragma unroll
    for (int o = 16; o > 0; o >>= 1) ss += __shfl_xor_sync(0xffffffffu, ss, o);
    float rs = rsqrtf(ss * (1.0f / D) + 1e-5f);
    float4 g = *reinterpret_cast<const float4*>(gamma + lane * 4);
    float4 b = *reinterpret_cast<const float4*>(beta + lane * 4);
    float4 o4;
    o4.x = d0 * rs * g.x + b.x;
    o4.y = d1 * rs * g.y + b.y;
    o4.z = d2 * rs * g.z + b.z;
    o4.w = d3 * rs * g.w + b.w;
    *reinterpret_cast<float4*>(g_h + (size_t)n * D + lane * 4) = o4;
}

// ---------------- kernel: node projections P = h @ [Wa | Wb] ----------------
__global__ __launch_bounds__(512, 1)
void pnode_kernel(const float* __restrict__ msg_w1) {
    extern __shared__ float smem[];
    float* sW = smem;
    float* sA = sW + 16384;

    const int tid = threadIdx.x;
    const int rg = tid >> 4;
    const int cg = tid & 15;
    const int n0 = blockIdx.x * 128;
    const int half_ = blockIdx.y;

    const float4* w4 = reinterpret_cast<const float4*>(msg_w1 + half_ * 128 * 128);
#pragma unroll
    for (int i = 0; i < 8; ++i)
        reinterpret_cast<float4*>(sW)[tid + i * 512] = w4[tid + i * 512];

    unsigned long long acc[4][4];
#pragma unroll
    for (int r = 0; r < 4; ++r)
#pragma unroll
        for (int p = 0; p < 4; ++p) acc[r][p] = 0ull;

    const int arow = tid >> 2;
    const int akk  = (tid & 3) * 4;

    for (int kc = 0; kc < 8; ++kc) {
        if (kc) __syncthreads();
        int n = n0 + arow;
        float4 v = make_float4(0.f, 0.f, 0.f, 0.f);
        if (n < N_NODES)
            v = *reinterpret_cast<const float4*>(g_h + (size_t)n * 128 + kc * 16 + akk);
        sA[(akk + 0) * 132 + arow] = v.x;
        sA[(akk + 1) * 132 + arow] = v.y;
        sA[(akk + 2) * 132 + arow] = v.z;
        sA[(akk + 3) * 132 + arow] = v.w;
        __syncthreads();
        mma16(sA, sW + kc * 16 * 128, rg, cg, acc);
    }

#pragma unroll
    for (int r = 0; r < 4; ++r) {
        int n = n0 + rg * 4 + r;
        if (n >= N_NODES) continue;
        float x[8];
        unpack_acc8(acc[r], x);
        float* dst = g_P + (size_t)n * 256 + half_ * 128 + cg * 8;
        *reinterpret_cast<float4*>(dst)     = make_float4(x[0], x[1], x[2], x[3]);
        *reinterpret_cast<float4*>(dst + 4) = make_float4(x[4], x[5], x[6], x[7]);
    }
}

// ---------------- kernel: per-src edge counts ----------------
__global__ void cnt_kernel(const int* __restrict__ src) {
    int i = blockIdx.x * blockDim.x + threadIdx.x;
    if (i < N_EDGES) atomicAdd(&g_cnt[src[i]], 1.0f);
}

// ---------------- kernel: pre-split weights to fp16 hi/lo, [n][KP] ----------
__global__ void wprep_kernel(const float* __restrict__ mw1,
                             const float* __restrict__ mw2) {
    int i = blockIdx.x * blockDim.x + threadIdx.x;
    if (i >= 32768) return;
    int mat = i >> 14;
    int r = i & 16383;
    int n = r >> 7;
    int k = r & 127;
    float v = (mat == 0) ? mw1[(256 + k) * 128 + n] : mw2[k * 128 + n];
    half h, l;
    split_h(v, h, l);
    int off = n * KP + k;
    if (mat == 0) { g_WcHi[off] = h; g_WcLo[off] = l; }
    else          { g_W2Hi[off] = h; g_W2Lo[off] = l; }
}

// ---------------- persistent fused edge MLP + scatter (wmma fp16 3-split) ----
// smem layout (bytes from 1024-aligned base):
//   weights persist for the whole kernel; staging aliases the A tiles.
#define SM_WCHI  0
#define SM_WCLO  34816
#define SM_W2HI  69632
#define SM_W2LO  104448
#define SM_A     139264                  // A_hi (34816), then A_lo
#define SM_ALO2  174080
#define SM_AUX   208896                  // sSrc 512 | sDst 512 | sB1 512 | sB2 512
#define EDGE_SMEM_P (208896 + 2048 + 1024)

// compute D = Ahi*Bhi + Alo*Bhi + Ahi*Blo and store fp32 result into staging.
// staging may alias the A tiles: sync after compute, before store.
__device__ __forceinline__ void gemm3_store(const half* __restrict__ aHi,
                                            const half* __restrict__ aLo,
                                            const half* __restrict__ bHi,
                                            const half* __restrict__ bLo,
                                            float* __restrict__ staging,
                                            int wm, int wn) {
    wmma::fragment<wmma::accumulator, 16, 16, 16, float> c[2][4];
#pragma unroll
    for (int i = 0; i < 2; ++i)
#pragma unroll
        for (int j = 0; j < 4; ++j) wmma::fill_fragment(c[i][j], 0.0f);

#pragma unroll
    for (int ks = 0; ks < 8; ++ks) {
        const int k0 = ks * 16;
        wmma::fragment<wmma::matrix_a, 16, 16, 16, half, wmma::row_major> ah[2], al[2];
#pragma unroll
        for (int i = 0; i < 2; ++i) {
            const int m0 = wm * 32 + i * 16;
            wmma::load_matrix_sync(ah[i], aHi + m0 * KP + k0, KP);
            wmma::load_matrix_sync(al[i], aLo + m0 * KP + k0, KP);
        }
#pragma unroll
        for (int j = 0; j < 4; ++j) {
            const int n0 = wn * 64 + j * 16;
            wmma::fragment<wmma::matrix_b, 16, 16, 16, half, wmma::col_major> bh, bl;
            wmma::load_matrix_sync(bh, bHi + n0 * KP + k0, KP);
            wmma::load_matrix_sync(bl, bLo + n0 * KP + k0, KP);
#pragma unroll
            for (int i = 0; i < 2; ++i) {
                wmma::mma_sync(c[i][j], ah[i], bh, c[i][j]);
                wmma::mma_sync(c[i][j], al[i], bh, c[i][j]);
                wmma::mma_sync(c[i][j], ah[i], bl, c[i][j]);
            }
        }
    }
    __syncthreads();   // all warps done reading A (staging aliases A)
#pragma unroll
    for (int i = 0; i < 2; ++i)
#pragma unroll
        for (int j = 0; j < 4; ++j)
            wmma::store_matrix_sync(staging + (wm * 32 + i * 16) * SP + wn * 64 + j * 16,
                                    c[i][j], SP, wmma::mem_row_major);
    __syncthreads();
}

__global__ __launch_bounds__(256, 1)
void edge_persist_kernel(const float* __restrict__ ef,
                         const float* __restrict__ b1, const float* __restrict__ b2,
                         const int* __restrict__ src, const int* __restrict__ dst) {
    extern __shared__ char smraw[];
    char* base = (char*)(((uintptr_t)smraw + 1023) & ~(uintptr_t)1023);

    half* sWcHi = (half*)(base + SM_WCHI);
    half* sWcLo = (half*)(base + SM_WCLO);
    half* sW2Hi = (half*)(base + SM_W2HI);
    half* sW2Lo = (half*)(base + SM_W2LO);
    half* sAHi  = (half*)(base + SM_A);
    half* sALo  = (half*)(base + SM_ALO2);
    float* staging = (float*)(base + SM_A);     // aliases A tiles
    int*   sSrc = (int*)(base + SM_AUX + 0);
    int*   sDst = (int*)(base + SM_AUX + 512);
    float* sB1  = (float*)(base + SM_AUX + 1024);
    float* sB2  = (float*)(base + SM_AUX + 1536);

    const int tid = threadIdx.x;
    const int wid = tid >> 5;
    const int wm = wid & 3;      // row group (32 rows)
    const int wn = wid >> 2;     // col group (64 cols)
    const int row = tid >> 1;    // 0..127
    const int c0 = (tid & 1) * 64;

    // ---- one-time: weights + biases into smem ----
    {
        const uint4* gw[4] = {(const uint4*)g_WcHi, (const uint4*)g_WcLo,
                              (const uint4*)g_W2Hi, (const uint4*)g_W2Lo};
        uint4* sw[4] = {(uint4*)sWcHi, (uint4*)sWcLo, (uint4*)sW2Hi, (uint4*)sW2Lo};
#pragma unroll
        for (int m = 0; m < 4; ++m)
            for (int idx = tid; idx < 2176; idx += 256)
                sw[m][idx] = gw[m][idx];
    }
    if (tid < 128) { sB1[tid] = b1[tid]; sB2[tid] = b2[tid]; }

    const int NT = N_EDGES / 128;  // 5000
    for (int t = blockIdx.x; t < NT; t += gridDim.x) {
        const int e0 = t * 128;
        __syncthreads();   // staging from previous tile fully consumed

        // indices + L2 prefetch of the P gather rows used in epilogue 1
        if (tid < 128) {
            int s = src[e0 + tid], d = dst[e0 + tid];
            sSrc[tid] = s;
            sDst[tid] = d;
            const char* pa = (const char*)(g_P + (size_t)s * 256);
            const char* pb = (const char*)(g_P + (size_t)d * 256 + 128);
#pragma unroll
            for (int q = 0; q < 4; ++q) {
                asm volatile("prefetch.global.L2 [%0];" :: "l"(pa + q * 128));
                asm volatile("prefetch.global.L2 [%0];" :: "l"(pb + q * 128));
            }
        }

        // ---- A tile: ef rows split to fp16 hi/lo ----
        {
            const float4* srcp = (const float4*)(ef + (size_t)(e0 + row) * 128 + c0);
            half* dh = sAHi + row * KP + c0;
            half* dl = sALo + row * KP + c0;
#pragma unroll
            for (int g = 0; g < 16; ++g) {
                float4 v = srcp[g];
                half h0, l0, h1, l1, h2, l2, h3, l3;
                split_h(v.x, h0, l0); split_h(v.y, h1, l1);
                split_h(v.z, h2, l2); split_h(v.w, h3, l3);
                *(uint2*)(dh + g * 4) = make_uint2(pack_h2(h0, h1), pack_h2(h2, h3));
                *(uint2*)(dl + g * 4) = make_uint2(pack_h2(l0, l1), pack_h2(l2, l3));
            }
        }
        __syncthreads();

        // ---- GEMM1: staging = ef @ Wc ----
        gemm3_store(sAHi, sALo, sWcHi, sWcLo, staging, wm, wn);

        // ---- epilogue 1 (in-place: read all staging first, then write fp16) ----
        float xs[64];
        {
            const float* st = staging + row * SP + c0;
#pragma unroll
            for (int g = 0; g < 16; ++g) {
                float4 v = *(const float4*)(st + g * 4);
                xs[g * 4 + 0] = v.x; xs[g * 4 + 1] = v.y;
                xs[g * 4 + 2] = v.z; xs[g * 4 + 3] = v.w;
            }
        }
        __syncthreads();   // all staging reads complete before overwriting
        {
            const int s = sSrc[row], dn = sDst[row];
            const float* pa = g_P + (size_t)s * 256 + c0;
            const float* pb = g_P + (size_t)dn * 256 + 128 + c0;
            half* dh = sAHi + row * KP + c0;
            half* dl = sALo + row * KP + c0;
#pragma unroll
            for (int g = 0; g < 16; ++g) {
                float4 A = *(const float4*)(pa + g * 4);
                float4 B = *(const float4*)(pb + g * 4);
                int c = c0 + g * 4;
                float x0 = silu_f(xs[g * 4 + 0] + A.x + B.x + sB1[c + 0]);
                float x1 = silu_f(xs[g * 4 + 1] + A.y + B.y + sB1[c + 1]);
                float x2 = silu_f(xs[g * 4 + 2] + A.z + B.z + sB1[c + 2]);
                float x3 = silu_f(xs[g * 4 + 3] + A.w + B.w + sB1[c + 3]);
                half h0, l0, h1, l1, h2, l2, h3, l3;
                split_h(x0, h0, l0); split_h(x1, h1, l1);
                split_h(x2, h2, l2); split_h(x3, h3, l3);
                *(uint2*)(dh + g * 4) = make_uint2(pack_h2(h0, h1), pack_h2(h2, h3));
                *(uint2*)(dl + g * 4) = make_uint2(pack_h2(l0, l1), pack_h2(l2, l3));
            }
        }
        __syncthreads();

        // ---- GEMM2: staging = m1 @ W2 ----
        gemm3_store(sAHi, sALo, sW2Hi, sW2Lo, staging, wm, wn);

        // ---- epilogue 2: msg = silu(staging + b2) -> scatter-add g_msum[src] ----
        {
            const int s = sSrc[row];
            const float* st = staging + row * SP + c0;
            float* outp = g_msum + (size_t)s * 128 + c0;
#pragma unroll
            for (int g = 0; g < 16; ++g) {
                float4 v = *(const float4*)(st + g * 4);
                int c = c0 + g * 4;
                red_add4(outp + g * 4,
                         silu_f(v.x + sB2[c + 0]), silu_f(v.y + sB2[c + 1]),
                         silu_f(v.z + sB2[c + 2]), silu_f(v.w + sB2[c + 3]));
            }
        }
    }
}

// ---------------- kernel: aggregation MLP + residual ----------------
__global__ __launch_bounds__(512, 1)
void agg_kernel(const float* __restrict__ nf,
                const float* __restrict__ agg_w1, const float* __restrict__ ab1,
                const float* __restrict__ agg_w2, const float* __restrict__ ab2,
                float* __restrict__ out) {
    extern __shared__ float smem[];
    float* sW  = smem;
    float* sA  = sW + 16384;
    float* sM1 = sA + 16 * 132;

    const int tid = threadIdx.x;
    const int rg = tid >> 4;
    const int cg = tid & 15;
    const int n0 = blockIdx.x * 128;
    const int arow = tid >> 2;
    const int akk  = (tid & 3) * 4;

    unsigned long long acc[4][4];
#pragma unroll
    for (int r = 0; r < 4; ++r)
#pragma unroll
        for (int p = 0; p < 4; ++p) acc[r][p] = 0ull;

    {
        const float4* w4 = reinterpret_cast<const float4*>(agg_w1);
#pragma unroll
        for (int i = 0; i < 8; ++i)
            reinterpret_cast<float4*>(sW)[tid + i * 512] = w4[tid + i * 512];
        for (int kc = 0; kc < 8; ++kc) {
            if (kc) __syncthreads();
            int n = n0 + arow;
            float4 v = make_float4(0.f, 0.f, 0.f, 0.f);
            if (n < N_NODES)
                v = *reinterpret_cast<const float4*>(g_h + (size_t)n * 128 + kc * 16 + akk);
            sA[(akk + 0) * 132 + arow] = v.x;
            sA[(akk + 1) * 132 + arow] = v.y;
            sA[(akk + 2) * 132 + arow] = v.z;
            sA[(akk + 3) * 132 + arow] = v.w;
            __syncthreads();
            mma16(sA, sW + kc * 16 * 128, rg, cg, acc);
        }
    }
    __syncthreads();

    {
        const float4* w4 = reinterpret_cast<const float4*>(agg_w1 + 128 * 128);
#pragma unroll
        for (int i = 0; i < 8; ++i)
            reinterpret_cast<float4*>(sW)[tid + i * 512] = w4[tid + i * 512];
        for (int kc = 0; kc < 8; ++kc) {
            if (kc) __syncthreads();
            int n = n0 + arow;
            float4 v = make_float4(0.f, 0.f, 0.f, 0.f);
            if (n < N_NODES) {
                v = *reinterpret_cast<const float4*>(g_msum + (size_t)n * 128 + kc * 16 + akk);
                float inv = 1.0f / fmaxf(g_cnt[n], 1.0f);
                v.x *= inv; v.y *= inv; v.z *= inv; v.w *= inv;
            }
            sA[(akk + 0) * 132 + arow] = v.x;
            sA[(akk + 1) * 132 + arow] = v.y;
            sA[(akk + 2) * 132 + arow] = v.z;
            sA[(akk + 3) * 132 + arow] = v.w;
            __syncthreads();
            mma16(sA, sW + kc * 16 * 128, rg, cg, acc);
        }
    }

    float bias[8];
#pragma unroll
    for (int c = 0; c < 8; ++c) bias[c] = ab1[cg * 8 + c];
#pragma unroll
    for (int r = 0; r < 4; ++r) {
        int rowi = rg * 4 + r;
        float x[8];
        unpack_acc8(acc[r], x);
        float* m = sM1 + rowi * 132 + cg * 8;
        *reinterpret_cast<float4*>(m) = make_float4(
            silu_f(x[0] + bias[0]), silu_f(x[1] + bias[1]),
            silu_f(x[2] + bias[2]), silu_f(x[3] + bias[3]));
        *reinterpret_cast<float4*>(m + 4) = make_float4(
            silu_f(x[4] + bias[4]), silu_f(x[5] + bias[5]),
            silu_f(x[6] + bias[6]), silu_f(x[7] + bias[7]));
    }
    __syncthreads();

    {
        const float4* w4 = reinterpret_cast<const float4*>(agg_w2);
#pragma unroll
        for (int i = 0; i < 8; ++i)
            reinterpret_cast<float4*>(sW)[tid + i * 512] = w4[tid + i * 512];
    }
    __syncthreads();

#pragma unroll
    for (int r = 0; r < 4; ++r)
#pragma unroll
        for (int p = 0; p < 4; ++p) acc[r][p] = 0ull;

    gemm2_128(sM1, sW, rg, cg, acc);

#pragma unroll
    for (int c = 0; c < 8; ++c) bias[c] = ab2[cg * 8 + c];
#pragma unroll
    for (int r = 0; r < 4; ++r) {
        int n = n0 + rg * 4 + r;
        if (n >= N_NODES) continue;
        float x[8];
        unpack_acc8(acc[r], x);
        const float* nfp = nf + (size_t)n * 128 + cg * 8;
        float4 f0 = *reinterpret_cast<const float4*>(nfp);
        float4 f1 = *reinterpret_cast<const float4*>(nfp + 4);
        float* o = out + (size_t)n * 128 + cg * 8;
        *reinterpret_cast<float4*>(o) = make_float4(
            f0.x + silu_f(x[0] + bias[0]), f0.y + silu_f(x[1] + bias[1]),
            f0.z + silu_f(x[2] + bias[2]), f0.w + silu_f(x[3] + bias[3]));
        *reinterpret_cast<float4*>(o + 4) = make_float4(
            f1.x + silu_f(x[4] + bias[4]), f1.y + silu_f(x[5] + bias[5]),
            f1.z + silu_f(x[6] + bias[6]), f1.w + silu_f(x[7] + bias[7]));
    }
}

// ---------------- launcher ----------------
extern "C" void kernel_launch(void* const* d_in, const int* in_sizes, int n_in,
                              void* d_out, int out_size) {
    (void)in_sizes; (void)n_in; (void)out_size;
    const float* nf  = (const float*)d_in[0];
    const float* ef  = (const float*)d_in[1];
    const float* gam = (const float*)d_in[2];
    const float* bet = (const float*)d_in[3];
    const float* mw1 = (const float*)d_in[4];
    const float* mb1 = (const float*)d_in[5];
    const float* mw2 = (const float*)d_in[6];
    const float* mb2 = (const float*)d_in[7];
    const float* aw1 = (const float*)d_in[8];
    const float* ab1 = (const float*)d_in[9];
    const float* aw2 = (const float*)d_in[10];
    const float* ab2 = (const float*)d_in[11];
    const int* eidx  = (const int*)d_in[12];
    const int* src = eidx;
    const int* dst = eidx + N_EDGES;
    float* out = (float*)d_out;

    const int AGG_SMEM = (16384 + 16 * 132 + 128 * 132) * 4;
    const int P_SMEM   = (16384 + 16 * 132) * 4;

    cudaFuncSetAttribute(edge_persist_kernel, cudaFuncAttributeMaxDynamicSharedMemorySize, EDGE_SMEM_P);
    cudaFuncSetAttribute(agg_kernel,   cudaFuncAttributeMaxDynamicSharedMemorySize, AGG_SMEM);
    cudaFuncSetAttribute(pnode_kernel, cudaFuncAttributeMaxDynamicSharedMemorySize, P_SMEM);

    const int NODE_TILES = (N_NODES + 127) / 128;  // 313

    zero_kernel<<<(N_NODES * D / 4 + 255) / 256, 256>>>();
    ln_kernel<<<N_NODES / 8, 256>>>(nf, gam, bet);
    wprep_kernel<<<128, 256>>>(mw1, mw2);
    pnode_kernel<<<dim3(NODE_TILES, 2), 512, P_SMEM>>>(mw1);
    cnt_kernel<<<(N_EDGES + 255) / 256, 256>>>(src);
    edge_persist_kernel<<<152, 256, EDGE_SMEM_P>>>(ef, mb1, mb2, src, dst);
    agg_kernel<<<NODE_TILES, 512, AGG_SMEM>>>(nf, aw1, ab1, aw2, ab2, out);
}

// round 5
// speedup vs baseline: 1.4170x; 1.0009x over previous
#include <cuda_runtime.h>
#include <cuda_fp16.h>
#include <mma.h>
#include <cstdint>

using namespace nvcuda;

// Problem constants
#define N_NODES 40000
#define N_EDGES 640000
#define D 128

// tile strides
#define KP 136           // half elements per row in A/W tiles (pad 8)
#define SP 132           // float elements per row in staging

// ---------------- device scratch ----------------
__device__ float g_h[N_NODES * D];
__device__ float g_P[N_NODES * 2 * D];
__device__ float g_msum[N_NODES * D];
__device__ float g_cnt[N_NODES];

// Pre-split fp16 weights, layout [n][KP] (B col-major for wmma), hi/lo parts.
__device__ __align__(32) half g_WcHi[128 * KP];
__device__ __align__(32) half g_WcLo[128 * KP];
__device__ __align__(32) half g_W2Hi[128 * KP];
__device__ __align__(32) half g_W2Lo[128 * KP];

// ---------------- generic helpers ----------------
__device__ __forceinline__ float silu_f(float x) {
    return x / (1.0f + __expf(-x));
}

__device__ __forceinline__ unsigned long long pack2(float x, float y) {
    unsigned long long r;
    asm("mov.b64 %0, {%1, %2};" : "=l"(r) : "f"(x), "f"(y));
    return r;
}

__device__ __forceinline__ void fma2(unsigned long long &d,
                                     unsigned long long a,
                                     unsigned long long b) {
    asm("fma.rn.f32x2 %0, %1, %2, %0;" : "+l"(d) : "l"(a), "l"(b));
}

__device__ __forceinline__ float2 unpack2(unsigned long long v) {
    float lo, hi;
    asm("mov.b64 {%0, %1}, %2;" : "=f"(lo), "=f"(hi) : "l"(v));
    return make_float2(lo, hi);
}

__device__ __forceinline__ void unpack_acc8(const unsigned long long a[4], float x[8]) {
    float2 t;
    t = unpack2(a[0]); x[0] = t.x; x[1] = t.y;
    t = unpack2(a[1]); x[2] = t.x; x[3] = t.y;
    t = unpack2(a[2]); x[4] = t.x; x[5] = t.y;
    t = unpack2(a[3]); x[6] = t.x; x[7] = t.y;
}

__device__ __forceinline__ void red_add4(float* p, float a, float b, float c, float d) {
    asm volatile("red.global.add.v4.f32 [%0], {%1, %2, %3, %4};"
                 :: "l"(p), "f"(a), "f"(b), "f"(c), "f"(d) : "memory");
}

__device__ __forceinline__ void split_h(float x, half &h, half &l) {
    h = __float2half_rn(x);
    l = __float2half_rn(x - __half2float(h));
}

__device__ __forceinline__ uint32_t pack_h2(half a, half b) {
    __half2 t = __halves2half2(a, b);
    return *reinterpret_cast<uint32_t*>(&t);
}

// ---------------- fp32 SIMT micro-GEMM (pnode/agg) ----------------
__device__ __forceinline__ void mma16(const float* __restrict__ sA,
                                      const float* __restrict__ sWk,
                                      int rg, int cg,
                                      unsigned long long acc[4][4]) {
#pragma unroll
    for (int k = 0; k < 16; ++k) {
        float4 a4 = *reinterpret_cast<const float4*>(sA + k * 132 + rg * 4);
        const float* wr = sWk + k * 128 + cg * 8;
        ulonglong2 b01 = *reinterpret_cast<const ulonglong2*>(wr);
        ulonglong2 b23 = *reinterpret_cast<const ulonglong2*>(wr + 4);
        float a[4] = {a4.x, a4.y, a4.z, a4.w};
#pragma unroll
        for (int r = 0; r < 4; ++r) {
            unsigned long long ap = pack2(a[r], a[r]);
            fma2(acc[r][0], ap, b01.x);
            fma2(acc[r][1], ap, b01.y);
            fma2(acc[r][2], ap, b23.x);
            fma2(acc[r][3], ap, b23.y);
        }
    }
}

__device__ __forceinline__ void gemm2_128(const float* __restrict__ sM1,
                                          const float* __restrict__ sW2,
                                          int rg, int cg,
                                          unsigned long long acc[4][4]) {
    const int r0 = rg * 4;
#pragma unroll 8
    for (int k = 0; k < 128; ++k) {
        const float* wr = sW2 + k * 128 + cg * 8;
        ulonglong2 b01 = *reinterpret_cast<const ulonglong2*>(wr);
        ulonglong2 b23 = *reinterpret_cast<const ulonglong2*>(wr + 4);
#pragma unroll
        for (int r = 0; r < 4; ++r) {
            float a = sM1[(r0 + r) * 132 + k];
            unsigned long long ap = pack2(a, a);
            fma2(acc[r][0], ap, b01.x);
            fma2(acc[r][1], ap, b01.y);
            fma2(acc[r][2], ap, b23.x);
            fma2(acc[r][3], ap, b23.y);
        }
    }
}

// ---------------- kernel: zero scratch ----------------
__global__ void zero_kernel() {
    int i = blockIdx.x * blockDim.x + threadIdx.x;
    const int total4 = N_NODES * D / 4;
    if (i < total4) reinterpret_cast<float4*>(g_msum)[i] = make_float4(0.f, 0.f, 0.f, 0.f);
    if (i < N_NODES) g_cnt[i] = 0.0f;
}

// ---------------- kernel: LayerNorm ----------------
__global__ void ln_kernel(const float* __restrict__ x,
                          const float* __restrict__ gamma,
                          const float* __restrict__ beta) {
    int warp = threadIdx.x >> 5;
    int lane = threadIdx.x & 31;
    int n = blockIdx.x * 8 + warp;
    float4 v = *reinterpret_cast<const float4*>(x + (size_t)n * D + lane * 4);
    float s = v.x + v.y + v.z + v.w;
#pragma unroll
    for (int o = 16; o > 0; o >>= 1) s += __shfl_xor_sync(0xffffffffu, s, o);
    float mu = s * (1.0f / D);
    float d0 = v.x - mu, d1 = v.y - mu, d2 = v.z - mu, d3 = v.w - mu;
    float ss = d0 * d0 + d1 * d1 + d2 * d2 + d3 * d3;
#pragma unroll
    for (int o = 16; o > 0; o >>= 1) ss += __shfl_xor_sync(0xffffffffu, ss, o);
    float rs = rsqrtf(ss * (1.0f / D) + 1e-5f);
    float4 g = *reinterpret_cast<const float4*>(gamma + lane * 4);
    float4 b = *reinterpret_cast<const float4*>(beta + lane * 4);
    float4 o4;
    o4.x = d0 * rs * g.x + b.x;
    o4.y = d1 * rs * g.y + b.y;
    o4.z = d2 * rs * g.z + b.z;
    o4.w = d3 * rs * g.w + b.w;
    *reinterpret_cast<float4*>(g_h + (size_t)n * D + lane * 4) = o4;
}

// ---------------- kernel: node projections P = h @ [Wa | Wb] ----------------
__global__ __launch_bounds__(512, 1)
void pnode_kernel(const float* __restrict__ msg_w1) {
    extern __shared__ float smem[];
    float* sW = smem;
    float* sA = sW + 16384;

    const int tid = threadIdx.x;
    const int rg = tid >> 4;
    const int cg = tid & 15;
    const int n0 = blockIdx.x * 128;
    const int half_ = blockIdx.y;

    const float4* w4 = reinterpret_cast<const float4*>(msg_w1 + half_ * 128 * 128);
#pragma unroll
    for (int i = 0; i < 8; ++i)
        reinterpret_cast<float4*>(sW)[tid + i * 512] = w4[tid + i * 512];

    unsigned long long acc[4][4];
#pragma unroll
    for (int r = 0; r < 4; ++r)
#pragma unroll
        for (int p = 0; p < 4; ++p) acc[r][p] = 0ull;

    const int arow = tid >> 2;
    const int akk  = (tid & 3) * 4;

    for (int kc = 0; kc < 8; ++kc) {
        if (kc) __syncthreads();
        int n = n0 + arow;
        float4 v = make_float4(0.f, 0.f, 0.f, 0.f);
        if (n < N_NODES)
            v = *reinterpret_cast<const float4*>(g_h + (size_t)n * 128 + kc * 16 + akk);
        sA[(akk + 0) * 132 + arow] = v.x;
        sA[(akk + 1) * 132 + arow] = v.y;
        sA[(akk + 2) * 132 + arow] = v.z;
        sA[(akk + 3) * 132 + arow] = v.w;
        __syncthreads();
        mma16(sA, sW + kc * 16 * 128, rg, cg, acc);
    }

#pragma unroll
    for (int r = 0; r < 4; ++r) {
        int n = n0 + rg * 4 + r;
        if (n >= N_NODES) continue;
        float x[8];
        unpack_acc8(acc[r], x);
        float* dst = g_P + (size_t)n * 256 + half_ * 128 + cg * 8;
        *reinterpret_cast<float4*>(dst)     = make_float4(x[0], x[1], x[2], x[3]);
        *reinterpret_cast<float4*>(dst + 4) = make_float4(x[4], x[5], x[6], x[7]);
    }
}

// ---------------- kernel: per-src edge counts ----------------
__global__ void cnt_kernel(const int* __restrict__ src) {
    int i = blockIdx.x * blockDim.x + threadIdx.x;
    if (i < N_EDGES) atomicAdd(&g_cnt[src[i]], 1.0f);
}

// ---------------- kernel: pre-split weights to fp16 hi/lo, [n][KP] ----------
__global__ void wprep_kernel(const float* __restrict__ mw1,
                             const float* __restrict__ mw2) {
    int i = blockIdx.x * blockDim.x + threadIdx.x;
    if (i >= 32768) return;
    int mat = i >> 14;
    int r = i & 16383;
    int n = r >> 7;
    int k = r & 127;
    float v = (mat == 0) ? mw1[(256 + k) * 128 + n] : mw2[k * 128 + n];
    half h, l;
    split_h(v, h, l);
    int off = n * KP + k;
    if (mat == 0) { g_WcHi[off] = h; g_WcLo[off] = l; }
    else          { g_W2Hi[off] = h; g_W2Lo[off] = l; }
}

// ---------------- persistent fused edge MLP + scatter (wmma fp16 3-split) ----
// smem layout (bytes from 1024-aligned base):
//   weights persist for the whole kernel; staging aliases the A tiles.
#define SM_WCHI  0
#define SM_WCLO  34816
#define SM_W2HI  69632
#define SM_W2LO  104448
#define SM_A     139264                  // A_hi (34816), then A_lo
#define SM_ALO2  174080
#define SM_AUX   208896                  // sSrc 512 | sDst 512 | sB1 512 | sB2 512
#define EDGE_SMEM_P (208896 + 2048 + 1024)

// compute D = Ahi*Bhi + Alo*Bhi + Ahi*Blo and store fp32 result into staging.
// staging may alias the A tiles: sync after compute, before store.
__device__ __forceinline__ void gemm3_store(const half* __restrict__ aHi,
                                            const half* __restrict__ aLo,
                                            const half* __restrict__ bHi,
                                            const half* __restrict__ bLo,
                                            float* __restrict__ staging,
                                            int wm, int wn) {
    wmma::fragment<wmma::accumulator, 16, 16, 16, float> c[2][4];
#pragma unroll
    for (int i = 0; i < 2; ++i)
#pragma unroll
        for (int j = 0; j < 4; ++j) wmma::fill_fragment(c[i][j], 0.0f);

#pragma unroll
    for (int ks = 0; ks < 8; ++ks) {
        const int k0 = ks * 16;
        wmma::fragment<wmma::matrix_a, 16, 16, 16, half, wmma::row_major> ah[2], al[2];
#pragma unroll
        for (int i = 0; i < 2; ++i) {
            const int m0 = wm * 32 + i * 16;
            wmma::load_matrix_sync(ah[i], aHi + m0 * KP + k0, KP);
            wmma::load_matrix_sync(al[i], aLo + m0 * KP + k0, KP);
        }
#pragma unroll
        for (int j = 0; j < 4; ++j) {
            const int n0 = wn * 64 + j * 16;
            wmma::fragment<wmma::matrix_b, 16, 16, 16, half, wmma::col_major> bh, bl;
            wmma::load_matrix_sync(bh, bHi + n0 * KP + k0, KP);
            wmma::load_matrix_sync(bl, bLo + n0 * KP + k0, KP);
#pragma unroll
            for (int i = 0; i < 2; ++i) {
                wmma::mma_sync(c[i][j], ah[i], bh, c[i][j]);
                wmma::mma_sync(c[i][j], al[i], bh, c[i][j]);
                wmma::mma_sync(c[i][j], ah[i], bl, c[i][j]);
            }
        }
    }
    __syncthreads();   // all warps done reading A (staging aliases A)
#pragma unroll
    for (int i = 0; i < 2; ++i)
#pragma unroll
        for (int j = 0; j < 4; ++j)
            wmma::store_matrix_sync(staging + (wm * 32 + i * 16) * SP + wn * 64 + j * 16,
                                    c[i][j], SP, wmma::mem_row_major);
    __syncthreads();
}

__global__ __launch_bounds__(256, 1)
void edge_persist_kernel(const float* __restrict__ ef,
                         const float* __restrict__ b1, const float* __restrict__ b2,
                         const int* __restrict__ src, const int* __restrict__ dst) {
    extern __shared__ char smraw[];
    char* base = (char*)(((uintptr_t)smraw + 1023) & ~(uintptr_t)1023);

    half* sWcHi = (half*)(base + SM_WCHI);
    half* sWcLo = (half*)(base + SM_WCLO);
    half* sW2Hi = (half*)(base + SM_W2HI);
    half* sW2Lo = (half*)(base + SM_W2LO);
    half* sAHi  = (half*)(base + SM_A);
    half* sALo  = (half*)(base + SM_ALO2);
    float* staging = (float*)(base + SM_A);     // aliases A tiles
    int*   sSrc = (int*)(base + SM_AUX + 0);
    int*   sDst = (int*)(base + SM_AUX + 512);
    float* sB1  = (float*)(base + SM_AUX + 1024);
    float* sB2  = (float*)(base + SM_AUX + 1536);

    const int tid = threadIdx.x;
    const int wid = tid >> 5;
    const int wm = wid & 3;      // row group (32 rows)
    const int wn = wid >> 2;     // col group (64 cols)
    const int row = tid >> 1;    // 0..127
    const int c0 = (tid & 1) * 64;

    // ---- one-time: weights + biases into smem ----
    {
        const uint4* gw[4] = {(const uint4*)g_WcHi, (const uint4*)g_WcLo,
                              (const uint4*)g_W2Hi, (const uint4*)g_W2Lo};
        uint4* sw[4] = {(uint4*)sWcHi, (uint4*)sWcLo, (uint4*)sW2Hi, (uint4*)sW2Lo};
#pragma unroll
        for (int m = 0; m < 4; ++m)
            for (int idx = tid; idx < 2176; idx += 256)
                sw[m][idx] = gw[m][idx];
    }
    if (tid < 128) { sB1[tid] = b1[tid]; sB2[tid] = b2[tid]; }

    const int NT = N_EDGES / 128;  // 5000
    for (int t = blockIdx.x; t < NT; t += gridDim.x) {
        const int e0 = t * 128;
        __syncthreads();   // staging from previous tile fully consumed

        // indices + L2 prefetch of the P gather rows used in epilogue 1
        if (tid < 128) {
            int s = src[e0 + tid], d = dst[e0 + tid];
            sSrc[tid] = s;
            sDst[tid] = d;
            const char* pa = (const char*)(g_P + (size_t)s * 256);
            const char* pb = (const char*)(g_P + (size_t)d * 256 + 128);
#pragma unroll
            for (int q = 0; q < 4; ++q) {
                asm volatile("prefetch.global.L2 [%0];" :: "l"(pa + q * 128));
                asm volatile("prefetch.global.L2 [%0];" :: "l"(pb + q * 128));
            }
        }

        // ---- A tile: ef rows split to fp16 hi/lo ----
        {
            const float4* srcp = (const float4*)(ef + (size_t)(e0 + row) * 128 + c0);
            half* dh = sAHi + row * KP + c0;
            half* dl = sALo + row * KP + c0;
#pragma unroll
            for (int g = 0; g < 16; ++g) {
                float4 v = srcp[g];
                half h0, l0, h1, l1, h2, l2, h3, l3;
                split_h(v.x, h0, l0); split_h(v.y, h1, l1);
                split_h(v.z, h2, l2); split_h(v.w, h3, l3);
                *(uint2*)(dh + g * 4) = make_uint2(pack_h2(h0, h1), pack_h2(h2, h3));
                *(uint2*)(dl + g * 4) = make_uint2(pack_h2(l0, l1), pack_h2(l2, l3));
            }
        }
        __syncthreads();

        // ---- GEMM1: staging = ef @ Wc ----
        gemm3_store(sAHi, sALo, sWcHi, sWcLo, staging, wm, wn);

        // ---- epilogue 1 (in-place: read all staging first, then write fp16) ----
        float xs[64];
        {
            const float* st = staging + row * SP + c0;
#pragma unroll
            for (int g = 0; g < 16; ++g) {
                float4 v = *(const float4*)(st + g * 4);
                xs[g * 4 + 0] = v.x; xs[g * 4 + 1] = v.y;
                xs[g * 4 + 2] = v.z; xs[g * 4 + 3] = v.w;
            }
        }
        __syncthreads();   // all staging reads complete before overwriting
        {
            const int s = sSrc[row], dn = sDst[row];
            const float* pa = g_P + (size_t)s * 256 + c0;
            const float* pb = g_P + (size_t)dn * 256 + 128 + c0;
            half* dh = sAHi + row * KP + c0;
            half* dl = sALo + row * KP + c0;
#pragma unroll
            for (int g = 0; g < 16; ++g) {
                float4 A = *(const float4*)(pa + g * 4);
                float4 B = *(const float4*)(pb + g * 4);
                int c = c0 + g * 4;
                float x0 = silu_f(xs[g * 4 + 0] + A.x + B.x + sB1[c + 0]);
                float x1 = silu_f(xs[g * 4 + 1] + A.y + B.y + sB1[c + 1]);
                float x2 = silu_f(xs[g * 4 + 2] + A.z + B.z + sB1[c + 2]);
                float x3 = silu_f(xs[g * 4 + 3] + A.w + B.w + sB1[c + 3]);
                half h0, l0, h1, l1, h2, l2, h3, l3;
                split_h(x0, h0, l0); split_h(x1, h1, l1);
                split_h(x2, h2, l2); split_h(x3, h3, l3);
                *(uint2*)(dh + g * 4) = make_uint2(pack_h2(h0, h1), pack_h2(h2, h3));
                *(uint2*)(dl + g * 4) = make_uint2(pack_h2(l0, l1), pack_h2(l2, l3));
            }
        }
        __syncthreads();

        // ---- GEMM2: staging = m1 @ W2 ----
        gemm3_store(sAHi, sALo, sW2Hi, sW2Lo, staging, wm, wn);

        // ---- epilogue 2: msg = silu(staging + b2) -> scatter-add g_msum[src] ----
        {
            const int s = sSrc[row];
            const float* st = staging + row * SP + c0;
            float* outp = g_msum + (size_t)s * 128 + c0;
#pragma unroll
            for (int g = 0; g < 16; ++g) {
                float4 v = *(const float4*)(st + g * 4);
                int c = c0 + g * 4;
                red_add4(outp + g * 4,
                         silu_f(v.x + sB2[c + 0]), silu_f(v.y + sB2[c + 1]),
                         silu_f(v.z + sB2[c + 2]), silu_f(v.w + sB2[c + 3]));
            }
        }
    }
}

// ---------------- kernel: aggregation MLP + residual ----------------
__global__ __launch_bounds__(512, 1)
void agg_kernel(const float* __restrict__ nf,
                const float* __restrict__ agg_w1, const float* __restrict__ ab1,
                const float* __restrict__ agg_w2, const float* __restrict__ ab2,
                float* __restrict__ out) {
    extern __shared__ float smem[];
    float* sW  = smem;
    float* sA  = sW + 16384;
    float* sM1 = sA + 16 * 132;

    const int tid = threadIdx.x;
    const int rg = tid >> 4;
    const int cg = tid & 15;
    const int n0 = blockIdx.x * 128;
    const int arow = tid >> 2;
    const int akk  = (tid & 3) * 4;

    unsigned long long acc[4][4];
#pragma unroll
    for (int r = 0; r < 4; ++r)
#pragma unroll
        for (int p = 0; p < 4; ++p) acc[r][p] = 0ull;

    {
        const float4* w4 = reinterpret_cast<const float4*>(agg_w1);
#pragma unroll
        for (int i = 0; i < 8; ++i)
            reinterpret_cast<float4*>(sW)[tid + i * 512] = w4[tid + i * 512];
        for (int kc = 0; kc < 8; ++kc) {
            if (kc) __syncthreads();
            int n = n0 + arow;
            float4 v = make_float4(0.f, 0.f, 0.f, 0.f);
            if (n < N_NODES)
                v = *reinterpret_cast<const float4*>(g_h + (size_t)n * 128 + kc * 16 + akk);
            sA[(akk + 0) * 132 + arow] = v.x;
            sA[(akk + 1) * 132 + arow] = v.y;
            sA[(akk + 2) * 132 + arow] = v.z;
            sA[(akk + 3) * 132 + arow] = v.w;
            __syncthreads();
            mma16(sA, sW + kc * 16 * 128, rg, cg, acc);
        }
    }
    __syncthreads();

    {
        const float4* w4 = reinterpret_cast<const float4*>(agg_w1 + 128 * 128);
#pragma unroll
        for (int i = 0; i < 8; ++i)
            reinterpret_cast<float4*>(sW)[tid + i * 512] = w4[tid + i * 512];
        for (int kc = 0; kc < 8; ++kc) {
            if (kc) __syncthreads();
            int n = n0 + arow;
            float4 v = make_float4(0.f, 0.f, 0.f, 0.f);
            if (n < N_NODES) {
                v = *reinterpret_cast<const float4*>(g_msum + (size_t)n * 128 + kc * 16 + akk);
                float inv = 1.0f / fmaxf(g_cnt[n], 1.0f);
                v.x *= inv; v.y *= inv; v.z *= inv; v.w *= inv;
            }
            sA[(akk + 0) * 132 + arow] = v.x;
            sA[(akk + 1) * 132 + arow] = v.y;
            sA[(akk + 2) * 132 + arow] = v.z;
            sA[(akk + 3) * 132 + arow] = v.w;
            __syncthreads();
            mma16(sA, sW + kc * 16 * 128, rg, cg, acc);
        }
    }

    float bias[8];
#pragma unroll
    for (int c = 0; c < 8; ++c) bias[c] = ab1[cg * 8 + c];
#pragma unroll
    for (int r = 0; r < 4; ++r) {
        int rowi = rg * 4 + r;
        float x[8];
        unpack_acc8(acc[r], x);
        float* m = sM1 + rowi * 132 + cg * 8;
        *reinterpret_cast<float4*>(m) = make_float4(
            silu_f(x[0] + bias[0]), silu_f(x[1] + bias[1]),
            silu_f(x[2] + bias[2]), silu_f(x[3] + bias[3]));
        *reinterpret_cast<float4*>(m + 4) = make_float4(
            silu_f(x[4] + bias[4]), silu_f(x[5] + bias[5]),
            silu_f(x[6] + bias[6]), silu_f(x[7] + bias[7]));
    }
    __syncthreads();

    {
        const float4* w4 = reinterpret_cast<const float4*>(agg_w2);
#pragma unroll
        for (int i = 0; i < 8; ++i)
            reinterpret_cast<float4*>(sW)[tid + i * 512] = w4[tid + i * 512];
    }
    __syncthreads();

#pragma unroll
    for (int r = 0; r < 4; ++r)
#pragma unroll
        for (int p = 0; p < 4; ++p) acc[r][p] = 0ull;

    gemm2_128(sM1, sW, rg, cg, acc);

#pragma unroll
    for (int c = 0; c < 8; ++c) bias[c] = ab2[cg * 8 + c];
#pragma unroll
    for (int r = 0; r < 4; ++r) {
        int n = n0 + rg * 4 + r;
        if (n >= N_NODES) continue;
        float x[8];
        unpack_acc8(acc[r], x);
        const float* nfp = nf + (size_t)n * 128 + cg * 8;
        float4 f0 = *reinterpret_cast<const float4*>(nfp);
        float4 f1 = *reinterpret_cast<const float4*>(nfp + 4);
        float* o = out + (size_t)n * 128 + cg * 8;
        *reinterpret_cast<float4*>(o) = make_float4(
            f0.x + silu_f(x[0] + bias[0]), f0.y + silu_f(x[1] + bias[1]),
            f0.z + silu_f(x[2] + bias[2]), f0.w + silu_f(x[3] + bias[3]));
        *reinterpret_cast<float4*>(o + 4) = make_float4(
            f1.x + silu_f(x[4] + bias[4]), f1.y + silu_f(x[5] + bias[5]),
            f1.z + silu_f(x[6] + bias[6]), f1.w + silu_f(x[7] + bias[7]));
    }
}

// ---------------- launcher ----------------
extern "C" void kernel_launch(void* const* d_in, const int* in_sizes, int n_in,
                              void* d_out, int out_size) {
    (void)in_sizes; (void)n_in; (void)out_size;
    const float* nf  = (const float*)d_in[0];
    const float* ef  = (const float*)d_in[1];
    const float* gam = (const float*)d_in[2];
    const float* bet = (const float*)d_in[3];
    const float* mw1 = (const float*)d_in[4];
    const float* mb1 = (const float*)d_in[5];
    const float* mw2 = (const float*)d_in[6];
    const float* mb2 = (const float*)d_in[7];
    const float* aw1 = (const float*)d_in[8];
    const float* ab1 = (const float*)d_in[9];
    const float* aw2 = (const float*)d_in[10];
    const float* ab2 = (const float*)d_in[11];
    const int* eidx  = (const int*)d_in[12];
    const int* src = eidx;
    const int* dst = eidx + N_EDGES;
    float* out = (float*)d_out;

    const int AGG_SMEM = (16384 + 16 * 132 + 128 * 132) * 4;
    const int P_SMEM   = (16384 + 16 * 132) * 4;

    cudaFuncSetAttribute(edge_persist_kernel, cudaFuncAttributeMaxDynamicSharedMemorySize, EDGE_SMEM_P);
    cudaFuncSetAttribute(agg_kernel,   cudaFuncAttributeMaxDynamicSharedMemorySize, AGG_SMEM);
    cudaFuncSetAttribute(pnode_kernel, cudaFuncAttributeMaxDynamicSharedMemorySize, P_SMEM);

    const int NODE_TILES = (N_NODES + 127) / 128;  // 313

    zero_kernel<<<(N_NODES * D / 4 + 255) / 256, 256>>>();
    ln_kernel<<<N_NODES / 8, 256>>>(nf, gam, bet);
    wprep_kernel<<<128, 256>>>(mw1, mw2);
    pnode_kernel<<<dim3(NODE_TILES, 2), 512, P_SMEM>>>(mw1);
    cnt_kernel<<<(N_EDGES + 255) / 256, 256>>>(src);
    edge_persist_kernel<<<152, 256, EDGE_SMEM_P>>>(ef, mb1, mb2, src, dst);
    agg_kernel<<<NODE_TILES, 512, AGG_SMEM>>>(nf, aw1, ab1, aw2, ab2, out);
}

// round 6
// speedup vs baseline: 1.6337x; 1.1530x over previous
#include <cuda_runtime.h>
#include <cuda_fp16.h>
#include <mma.h>
#include <cstdint>

using namespace nvcuda;

// Problem constants
#define N_NODES 40000
#define NPAD    40064          // padded row count (multiple of 128)
#define N_EDGES 640000
#define D 128

// tile strides
#define KP 136           // half elements per row in A/W tiles (pad 8)
#define SP 132           // float elements per row in staging

// ---------------- device scratch ----------------
__device__ float g_h[NPAD * D];
__device__ float g_P[NPAD * 2 * D];
__device__ float g_msum[NPAD * D];
__device__ float g_cnt[NPAD];

// Pre-split fp16 weight tiles, layout [n][KP] (B col-major for wmma), hi/lo.
// Each tile: 128*KP halves = 34816 bytes.
__device__ __align__(32) half g_WcHi[128 * KP];   // msg_w1 rows [256,384)
__device__ __align__(32) half g_WcLo[128 * KP];
__device__ __align__(32) half g_W2Hi[128 * KP];   // msg_w2
__device__ __align__(32) half g_W2Lo[128 * KP];
__device__ __align__(32) half g_WaHi[128 * KP];   // msg_w1 rows [0,128)
__device__ __align__(32) half g_WaLo[128 * KP];
__device__ __align__(32) half g_WbHi[128 * KP];   // msg_w1 rows [128,256)
__device__ __align__(32) half g_WbLo[128 * KP];
__device__ __align__(32) half g_A1aHi[128 * KP];  // agg_w1 rows [0,128)
__device__ __align__(32) half g_A1aLo[128 * KP];
__device__ __align__(32) half g_A1bHi[128 * KP];  // agg_w1 rows [128,256)
__device__ __align__(32) half g_A1bLo[128 * KP];
__device__ __align__(32) half g_A2Hi[128 * KP];   // agg_w2
__device__ __align__(32) half g_A2Lo[128 * KP];

// ---------------- generic helpers ----------------
__device__ __forceinline__ float silu_f(float x) {
    return x / (1.0f + __expf(-x));
}

__device__ __forceinline__ void red_add4(float* p, float a, float b, float c, float d) {
    asm volatile("red.global.add.v4.f32 [%0], {%1, %2, %3, %4};"
                 :: "l"(p), "f"(a), "f"(b), "f"(c), "f"(d) : "memory");
}

__device__ __forceinline__ void split_h(float x, half &h, half &l) {
    h = __float2half_rn(x);
    l = __float2half_rn(x - __half2float(h));
}

__device__ __forceinline__ uint32_t pack_h2(half a, half b) {
    __half2 t = __halves2half2(a, b);
    return *reinterpret_cast<uint32_t*>(&t);
}

// ---------------- wmma building blocks ----------------
typedef wmma::fragment<wmma::accumulator, 16, 16, 16, float> FragC;
typedef wmma::fragment<wmma::matrix_a, 16, 16, 16, half, wmma::row_major> FragA;
typedef wmma::fragment<wmma::matrix_b, 16, 16, 16, half, wmma::col_major> FragB;

// c += Ahi*Bhi + Alo*Bhi + Ahi*Blo   (3-product split, ~1e-7 error)
__device__ __forceinline__ void gemm3_acc(const half* __restrict__ aHi,
                                          const half* __restrict__ aLo,
                                          const half* __restrict__ bHi,
                                          const half* __restrict__ bLo,
                                          FragC c[2][4], int wm, int wn) {
#pragma unroll
    for (int ks = 0; ks < 8; ++ks) {
        const int k0 = ks * 16;
        FragA ah[2], al[2];
#pragma unroll
        for (int i = 0; i < 2; ++i) {
            const int m0 = wm * 32 + i * 16;
            wmma::load_matrix_sync(ah[i], aHi + m0 * KP + k0, KP);
            wmma::load_matrix_sync(al[i], aLo + m0 * KP + k0, KP);
        }
#pragma unroll
        for (int j = 0; j < 4; ++j) {
            const int n0 = wn * 64 + j * 16;
            FragB bh, bl;
            wmma::load_matrix_sync(bh, bHi + n0 * KP + k0, KP);
            wmma::load_matrix_sync(bl, bLo + n0 * KP + k0, KP);
#pragma unroll
            for (int i = 0; i < 2; ++i) {
                wmma::mma_sync(c[i][j], ah[i], bh, c[i][j]);
                wmma::mma_sync(c[i][j], al[i], bh, c[i][j]);
                wmma::mma_sync(c[i][j], ah[i], bl, c[i][j]);
            }
        }
    }
}

// c += A*Bhi + A*Blo   (2-product: A single fp16, weights exactly split)
__device__ __forceinline__ void gemm2p_acc(const half* __restrict__ aH,
                                           const half* __restrict__ bHi,
                                           const half* __restrict__ bLo,
                                           FragC c[2][4], int wm, int wn) {
#pragma unroll
    for (int ks = 0; ks < 8; ++ks) {
        const int k0 = ks * 16;
        FragA ah[2];
#pragma unroll
        for (int i = 0; i < 2; ++i)
            wmma::load_matrix_sync(ah[i], aH + (wm * 32 + i * 16) * KP + k0, KP);
#pragma unroll
        for (int j = 0; j < 4; ++j) {
            const int n0 = wn * 64 + j * 16;
            FragB bh, bl;
            wmma::load_matrix_sync(bh, bHi + n0 * KP + k0, KP);
            wmma::load_matrix_sync(bl, bLo + n0 * KP + k0, KP);
#pragma unroll
            for (int i = 0; i < 2; ++i) {
                wmma::mma_sync(c[i][j], ah[i], bh, c[i][j]);
                wmma::mma_sync(c[i][j], ah[i], bl, c[i][j]);
            }
        }
    }
}

__device__ __forceinline__ void zero_frags(FragC c[2][4]) {
#pragma unroll
    for (int i = 0; i < 2; ++i)
#pragma unroll
        for (int j = 0; j < 4; ++j) wmma::fill_fragment(c[i][j], 0.0f);
}

__device__ __forceinline__ void store_stage(FragC c[2][4], float* st, int wm, int wn) {
#pragma unroll
    for (int i = 0; i < 2; ++i)
#pragma unroll
        for (int j = 0; j < 4; ++j)
            wmma::store_matrix_sync(st + (wm * 32 + i * 16) * SP + wn * 64 + j * 16,
                                    c[i][j], SP, wmma::mem_row_major);
}

// copy one 34816B weight tile global->smem (256 threads)
__device__ __forceinline__ void copy_tile(half* dst, const half* src, int tid) {
    uint4* d = (uint4*)dst;
    const uint4* s = (const uint4*)src;
#pragma unroll 2
    for (int idx = tid; idx < 2176; idx += 256) d[idx] = s[idx];
}

// ---------------- kernel: zero scratch (+ pad rows of g_h) ----------------
__global__ void zero_kernel() {
    int i = blockIdx.x * blockDim.x + threadIdx.x;
    const int total4 = NPAD * D / 4;
    if (i < total4) reinterpret_cast<float4*>(g_msum)[i] = make_float4(0.f, 0.f, 0.f, 0.f);
    if (i < NPAD) g_cnt[i] = 0.0f;
    if (i < (NPAD - N_NODES) * D / 4)
        reinterpret_cast<float4*>(g_h + N_NODES * D)[i] = make_float4(0.f, 0.f, 0.f, 0.f);
}

// ---------------- kernel: LayerNorm ----------------
__global__ void ln_kernel(const float* __restrict__ x,
                          const float* __restrict__ gamma,
                          const float* __restrict__ beta) {
    int warp = threadIdx.x >> 5;
    int lane = threadIdx.x & 31;
    int n = blockIdx.x * 8 + warp;
    float4 v = *reinterpret_cast<const float4*>(x + (size_t)n * D + lane * 4);
    float s = v.x + v.y + v.z + v.w;
#pragma unroll
    for (int o = 16; o > 0; o >>= 1) s += __shfl_xor_sync(0xffffffffu, s, o);
    float mu = s * (1.0f / D);
    float d0 = v.x - mu, d1 = v.y - mu, d2 = v.z - mu, d3 = v.w - mu;
    float ss = d0 * d0 + d1 * d1 + d2 * d2 + d3 * d3;
#pragma unroll
    for (int o = 16; o > 0; o >>= 1) ss += __shfl_xor_sync(0xffffffffu, ss, o);
    float rs = rsqrtf(ss * (1.0f / D) + 1e-5f);
    float4 g = *reinterpret_cast<const float4*>(gamma + lane * 4);
    float4 b = *reinterpret_cast<const float4*>(beta + lane * 4);
    float4 o4;
    o4.x = d0 * rs * g.x + b.x;
    o4.y = d1 * rs * g.y + b.y;
    o4.z = d2 * rs * g.z + b.z;
    o4.w = d3 * rs * g.w + b.w;
    *reinterpret_cast<float4*>(g_h + (size_t)n * D + lane * 4) = o4;
}

// ---------------- kernel: per-src edge counts ----------------
__global__ void cnt_kernel(const int* __restrict__ src) {
    int i = blockIdx.x * blockDim.x + threadIdx.x;
    if (i < N_EDGES) atomicAdd(&g_cnt[src[i]], 1.0f);
}

// ---------------- kernel: split all weights to fp16 hi/lo tiles ------------
__global__ void wprep_kernel(const float* __restrict__ mw1, const float* __restrict__ mw2,
                             const float* __restrict__ aw1, const float* __restrict__ aw2) {
    int i = blockIdx.x * blockDim.x + threadIdx.x;
    if (i >= 7 * 16384) return;
    int mat = i >> 14;
    int r = i & 16383;
    int n = r >> 7;
    int k = r & 127;
    float v;
    half *dh, *dl;
    switch (mat) {
        case 0: v = mw1[(256 + k) * 128 + n]; dh = g_WcHi;  dl = g_WcLo;  break;
        case 1: v = mw2[k * 128 + n];         dh = g_W2Hi;  dl = g_W2Lo;  break;
        case 2: v = mw1[k * 128 + n];         dh = g_WaHi;  dl = g_WaLo;  break;
        case 3: v = mw1[(128 + k) * 128 + n]; dh = g_WbHi;  dl = g_WbLo;  break;
        case 4: v = aw1[k * 128 + n];         dh = g_A1aHi; dl = g_A1aLo; break;
        case 5: v = aw1[(128 + k) * 128 + n]; dh = g_A1bHi; dl = g_A1bLo; break;
        default: v = aw2[k * 128 + n];        dh = g_A2Hi;  dl = g_A2Lo;  break;
    }
    half h, l;
    split_h(v, h, l);
    dh[n * KP + k] = h;
    dl[n * KP + k] = l;
}

// ---------------- kernel: node projections P = h @ [Wa|Wb] (wmma 3-split) ---
// smem: 4 weight tiles [0,139264) + A hi [139264,+34816) + A lo [174080,+34816)
#define PNODE_SMEM (208896 + 1024)
__global__ __launch_bounds__(256, 1)
void pnode_kernel() {
    extern __shared__ char smraw[];
    char* base = (char*)(((uintptr_t)smraw + 1023) & ~(uintptr_t)1023);
    half* sWaHi = (half*)(base + 0);
    half* sWaLo = (half*)(base + 34816);
    half* sWbHi = (half*)(base + 69632);
    half* sWbLo = (half*)(base + 104448);
    half* aHi   = (half*)(base + 139264);
    half* aLo   = (half*)(base + 174080);

    const int tid = threadIdx.x;
    const int wid = tid >> 5;
    const int wm = wid & 3;
    const int wn = wid >> 2;
    const int row = tid >> 1;
    const int c0 = (tid & 1) * 64;
    const int n0 = blockIdx.x * 128;

    copy_tile(sWaHi, g_WaHi, tid);
    copy_tile(sWaLo, g_WaLo, tid);
    copy_tile(sWbHi, g_WbHi, tid);
    copy_tile(sWbLo, g_WbLo, tid);

    // A = h tile, split hi/lo (padded globals: no bounds checks)
    {
        const float4* srcp = (const float4*)(g_h + (size_t)(n0 + row) * 128 + c0);
        half* dh = aHi + row * KP + c0;
        half* dl = aLo + row * KP + c0;
#pragma unroll
        for (int g = 0; g < 16; ++g) {
            float4 v = srcp[g];
            half h0, l0, h1, l1, h2, l2, h3, l3;
            split_h(v.x, h0, l0); split_h(v.y, h1, l1);
            split_h(v.z, h2, l2); split_h(v.w, h3, l3);
            *(uint2*)(dh + g * 4) = make_uint2(pack_h2(h0, h1), pack_h2(h2, h3));
            *(uint2*)(dl + g * 4) = make_uint2(pack_h2(l0, l1), pack_h2(l2, l3));
        }
    }
    __syncthreads();

#pragma unroll
    for (int hf = 0; hf < 2; ++hf) {
        FragC c[2][4];
        zero_frags(c);
        gemm3_acc(aHi, aLo, hf ? sWbHi : sWaHi, hf ? sWbLo : sWaLo, c, wm, wn);
#pragma unroll
        for (int i = 0; i < 2; ++i)
#pragma unroll
            for (int j = 0; j < 4; ++j)
                wmma::store_matrix_sync(
                    g_P + (size_t)(n0 + wm * 32 + i * 16) * 256 + hf * 128 + wn * 64 + j * 16,
                    c[i][j], 256, wmma::mem_row_major);
    }
}

// ---------------- persistent fused edge MLP + scatter (2-product wmma) ------
// smem: weights [0,139264) | A fp16 [139264,+34816) | staging f32 aliases A
//       [139264, 206848) | aux at 206848
#define SM_A    139264
#define SM_AUXE 206848
#define EDGE_SMEM (206848 + 2048 + 1024)

__global__ __launch_bounds__(256, 1)
void edge_persist_kernel(const float* __restrict__ ef,
                         const float* __restrict__ b1, const float* __restrict__ b2,
                         const int* __restrict__ src, const int* __restrict__ dst) {
    extern __shared__ char smraw[];
    char* base = (char*)(((uintptr_t)smraw + 1023) & ~(uintptr_t)1023);

    half* sWcHi = (half*)(base + 0);
    half* sWcLo = (half*)(base + 34816);
    half* sW2Hi = (half*)(base + 69632);
    half* sW2Lo = (half*)(base + 104448);
    half* sA    = (half*)(base + SM_A);
    float* stg  = (float*)(base + SM_A);      // aliases A
    int*   sSrc = (int*)(base + SM_AUXE + 0);
    int*   sDst = (int*)(base + SM_AUXE + 512);
    float* sB1  = (float*)(base + SM_AUXE + 1024);
    float* sB2  = (float*)(base + SM_AUXE + 1536);

    const int tid = threadIdx.x;
    const int wid = tid >> 5;
    const int wm = wid & 3;
    const int wn = wid >> 2;
    const int row = tid >> 1;
    const int c0 = (tid & 1) * 64;

    copy_tile(sWcHi, g_WcHi, tid);
    copy_tile(sWcLo, g_WcLo, tid);
    copy_tile(sW2Hi, g_W2Hi, tid);
    copy_tile(sW2Lo, g_W2Lo, tid);
    if (tid < 128) { sB1[tid] = b1[tid]; sB2[tid] = b2[tid]; }

    const int NT = N_EDGES / 128;  // 5000
    for (int t = blockIdx.x; t < NT; t += gridDim.x) {
        const int e0 = t * 128;
        __syncthreads();   // prev tile's staging/sSrc fully consumed

        // indices + L2 prefetch of P gather rows
        if (tid < 128) {
            int s = src[e0 + tid], d = dst[e0 + tid];
            sSrc[tid] = s;
            sDst[tid] = d;
            const char* pa = (const char*)(g_P + (size_t)s * 256);
            const char* pb = (const char*)(g_P + (size_t)d * 256 + 128);
#pragma unroll
            for (int q = 0; q < 4; ++q) {
                asm volatile("prefetch.global.L2 [%0];" :: "l"(pa + q * 128));
                asm volatile("prefetch.global.L2 [%0];" :: "l"(pb + q * 128));
            }
        }

        // A tile: ef rows -> single fp16
        {
            const float4* srcp = (const float4*)(ef + (size_t)(e0 + row) * 128 + c0);
            half* dh = sA + row * KP + c0;
#pragma unroll
            for (int g = 0; g < 16; ++g) {
                float4 v = srcp[g];
                *(uint2*)(dh + g * 4) =
                    make_uint2(pack_h2(__float2half_rn(v.x), __float2half_rn(v.y)),
                               pack_h2(__float2half_rn(v.z), __float2half_rn(v.w)));
            }
        }
        // prefetch next tile's ef into L2 while GEMMs run
        {
            int nt2 = t + gridDim.x;
            if (nt2 < NT) {
                const char* nef = (const char*)ef + (size_t)nt2 * 128 * 512;
                asm volatile("prefetch.global.L2 [%0];" :: "l"(nef + tid * 256));
                asm volatile("prefetch.global.L2 [%0];" :: "l"(nef + tid * 256 + 128));
            }
        }
        __syncthreads();

        // ---- GEMM1: stg = ef @ Wc ----
        FragC c[2][4];
        zero_frags(c);
        gemm2p_acc(sA, sWcHi, sWcLo, c, wm, wn);
        __syncthreads();           // all warps done reading A (stg aliases A)
        store_stage(c, stg, wm, wn);
        __syncthreads();

        // ---- epilogue 1: m1 = silu(stg + Pa[src] + Pb[dst] + b1) -> sA fp16
        float xs[64];
        {
            const float* st = stg + row * SP + c0;
#pragma unroll
            for (int g = 0; g < 16; ++g) {
                float4 v = *(const float4*)(st + g * 4);
                xs[g * 4 + 0] = v.x; xs[g * 4 + 1] = v.y;
                xs[g * 4 + 2] = v.z; xs[g * 4 + 3] = v.w;
            }
        }
        __syncthreads();           // all staging reads complete before overwrite
        {
            const int s = sSrc[row], dn = sDst[row];
            const float* pa = g_P + (size_t)s * 256 + c0;
            const float* pb = g_P + (size_t)dn * 256 + 128 + c0;
            half* dh = sA + row * KP + c0;
#pragma unroll
            for (int g = 0; g < 16; ++g) {
                float4 A = *(const float4*)(pa + g * 4);
                float4 B = *(const float4*)(pb + g * 4);
                int cc = c0 + g * 4;
                float x0 = silu_f(xs[g * 4 + 0] + A.x + B.x + sB1[cc + 0]);
                float x1 = silu_f(xs[g * 4 + 1] + A.y + B.y + sB1[cc + 1]);
                float x2 = silu_f(xs[g * 4 + 2] + A.z + B.z + sB1[cc + 2]);
                float x3 = silu_f(xs[g * 4 + 3] + A.w + B.w + sB1[cc + 3]);
                *(uint2*)(dh + g * 4) =
                    make_uint2(pack_h2(__float2half_rn(x0), __float2half_rn(x1)),
                               pack_h2(__float2half_rn(x2), __float2half_rn(x3)));
            }
        }
        __syncthreads();

        // ---- GEMM2: stg = m1 @ W2 ----
        zero_frags(c);
        gemm2p_acc(sA, sW2Hi, sW2Lo, c, wm, wn);
        __syncthreads();
        store_stage(c, stg, wm, wn);
        __syncthreads();

        // ---- epilogue 2: scatter-add silu(stg + b2) into g_msum[src] ----
        {
            const int s = sSrc[row];
            const float* st = stg + row * SP + c0;
            float* outp = g_msum + (size_t)s * 128 + c0;
#pragma unroll
            for (int g = 0; g < 16; ++g) {
                float4 v = *(const float4*)(st + g * 4);
                int cc = c0 + g * 4;
                red_add4(outp + g * 4,
                         silu_f(v.x + sB2[cc + 0]), silu_f(v.y + sB2[cc + 1]),
                         silu_f(v.z + sB2[cc + 2]), silu_f(v.w + sB2[cc + 3]));
            }
        }
    }
}

// ---------------- kernel: aggregation MLP + residual (wmma 3-split) ---------
// smem: 4 weight tiles [0,139264) | A hi/lo [139264..208896) | staging aliases
//       A [139264,206848) | aux at 208896
#define AGG_SMEM (208896 + 1024 + 1024)
__global__ __launch_bounds__(256, 1)
void agg_kernel(const float* __restrict__ nf,
                const float* __restrict__ ab1, const float* __restrict__ ab2,
                float* __restrict__ out) {
    extern __shared__ char smraw[];
    char* base = (char*)(((uintptr_t)smraw + 1023) & ~(uintptr_t)1023);
    half* T0  = (half*)(base + 0);
    half* T1  = (half*)(base + 34816);
    half* T2  = (half*)(base + 69632);
    half* T3  = (half*)(base + 104448);
    half* aHi = (half*)(base + 139264);
    half* aLo = (half*)(base + 174080);
    float* stg = (float*)(base + 139264);     // aliases A hi/lo
    float* sB1 = (float*)(base + 208896);
    float* sB2 = (float*)(base + 209408);

    const int tid = threadIdx.x;
    const int wid = tid >> 5;
    const int wm = wid & 3;
    const int wn = wid >> 2;
    const int row = tid >> 1;
    const int c0 = (tid & 1) * 64;
    const int n0 = blockIdx.x * 128;

    copy_tile(T0, g_A1aHi, tid);
    copy_tile(T1, g_A1aLo, tid);
    copy_tile(T2, g_A1bHi, tid);
    copy_tile(T3, g_A1bLo, tid);
    if (tid < 128) { sB1[tid] = ab1[tid]; sB2[tid] = ab2[tid]; }

    // A = h tile (padded: no bounds checks)
    {
        const float4* srcp = (const float4*)(g_h + (size_t)(n0 + row) * 128 + c0);
        half* dh = aHi + row * KP + c0;
        half* dl = aLo + row * KP + c0;
#pragma unroll
        for (int g = 0; g < 16; ++g) {
            float4 v = srcp[g];
            half h0, l0, h1, l1, h2, l2, h3, l3;
            split_h(v.x, h0, l0); split_h(v.y, h1, l1);
            split_h(v.z, h2, l2); split_h(v.w, h3, l3);
            *(uint2*)(dh + g * 4) = make_uint2(pack_h2(h0, h1), pack_h2(h2, h3));
            *(uint2*)(dl + g * 4) = make_uint2(pack_h2(l0, l1), pack_h2(l2, l3));
        }
    }
    __syncthreads();

    FragC c[2][4];
    zero_frags(c);
    gemm3_acc(aHi, aLo, T0, T1, c, wm, wn);     // h @ agg_w1[:128]
    __syncthreads();                            // done reading A

    // A = mean tile
    {
        float inv = 1.0f / fmaxf(g_cnt[n0 + row], 1.0f);
        const float4* srcp = (const float4*)(g_msum + (size_t)(n0 + row) * 128 + c0);
        half* dh = aHi + row * KP + c0;
        half* dl = aLo + row * KP + c0;
#pragma unroll
        for (int g = 0; g < 16; ++g) {
            float4 v = srcp[g];
            v.x *= inv; v.y *= inv; v.z *= inv; v.w *= inv;
            half h0, l0, h1, l1, h2, l2, h3, l3;
            split_h(v.x, h0, l0); split_h(v.y, h1, l1);
            split_h(v.z, h2, l2); split_h(v.w, h3, l3);
            *(uint2*)(dh + g * 4) = make_uint2(pack_h2(h0, h1), pack_h2(h2, h3));
            *(uint2*)(dl + g * 4) = make_uint2(pack_h2(l0, l1), pack_h2(l2, l3));
        }
    }
    __syncthreads();
    gemm3_acc(aHi, aLo, T2, T3, c, wm, wn);     // += mean @ agg_w1[128:]
    __syncthreads();                            // done reading A + T0/T1 long ago

    store_stage(c, stg, wm, wn);
    copy_tile(T0, g_A2Hi, tid);                 // overwrite with agg_w2
    copy_tile(T1, g_A2Lo, tid);
    __syncthreads();

    // epilogue 1: m1 = silu(stg + ab1) -> A hi/lo (aliases stg: read-all first)
    float xs[64];
    {
        const float* st = stg + row * SP + c0;
#pragma unroll
        for (int g = 0; g < 16; ++g) {
            float4 v = *(const float4*)(st + g * 4);
            xs[g * 4 + 0] = v.x; xs[g * 4 + 1] = v.y;
            xs[g * 4 + 2] = v.z; xs[g * 4 + 3] = v.w;
        }
    }
    __syncthreads();
    {
        half* dh = aHi + row * KP + c0;
        half* dl = aLo + row * KP + c0;
#pragma unroll
        for (int g = 0; g < 16; ++g) {
            int cc = c0 + g * 4;
            float x0 = silu_f(xs[g * 4 + 0] + sB1[cc + 0]);
            float x1 = silu_f(xs[g * 4 + 1] + sB1[cc + 1]);
            float x2 = silu_f(xs[g * 4 + 2] + sB1[cc + 2]);
            float x3 = silu_f(xs[g * 4 + 3] + sB1[cc + 3]);
            half h0, l0, h1, l1, h2, l2, h3, l3;
            split_h(x0, h0, l0); split_h(x1, h1, l1);
            split_h(x2, h2, l2); split_h(x3, h3, l3);
            *(uint2*)(dh + g * 4) = make_uint2(pack_h2(h0, h1), pack_h2(h2, h3));
            *(uint2*)(dl + g * 4) = make_uint2(pack_h2(l0, l1), pack_h2(l2, l3));
        }
    }
    __syncthreads();

    zero_frags(c);
    gemm3_acc(aHi, aLo, T0, T1, c, wm, wn);     // m1 @ agg_w2
    __syncthreads();
    store_stage(c, stg, wm, wn);
    __syncthreads();

    // epilogue 2: out = nf + silu(stg + ab2)
    {
        int n = n0 + row;
        if (n < N_NODES) {
            const float* st = stg + row * SP + c0;
            const float* nfp = nf + (size_t)n * 128 + c0;
            float* o = out + (size_t)n * 128 + c0;
#pragma unroll
            for (int g = 0; g < 16; ++g) {
                float4 v = *(const float4*)(st + g * 4);
                float4 f = *(const float4*)(nfp + g * 4);
                int cc = c0 + g * 4;
                float4 r;
                r.x = f.x + silu_f(v.x + sB2[cc + 0]);
                r.y = f.y + silu_f(v.y + sB2[cc + 1]);
                r.z = f.z + silu_f(v.z + sB2[cc + 2]);
                r.w = f.w + silu_f(v.w + sB2[cc + 3]);
                *(float4*)(o + g * 4) = r;
            }
        }
    }
}

// ---------------- launcher ----------------
extern "C" void kernel_launch(void* const* d_in, const int* in_sizes, int n_in,
                              void* d_out, int out_size) {
    (void)in_sizes; (void)n_in; (void)out_size;
    const float* nf  = (const float*)d_in[0];
    const float* ef  = (const float*)d_in[1];
    const float* gam = (const float*)d_in[2];
    const float* bet = (const float*)d_in[3];
    const float* mw1 = (const float*)d_in[4];
    const float* mb1 = (const float*)d_in[5];
    const float* mw2 = (const float*)d_in[6];
    const float* mb2 = (const float*)d_in[7];
    const float* aw1 = (const float*)d_in[8];
    const float* ab1 = (const float*)d_in[9];
    const float* aw2 = (const float*)d_in[10];
    const float* ab2 = (const float*)d_in[11];
    const int* eidx  = (const int*)d_in[12];
    const int* src = eidx;
    const int* dst = eidx + N_EDGES;
    float* out = (float*)d_out;

    cudaFuncSetAttribute(edge_persist_kernel, cudaFuncAttributeMaxDynamicSharedMemorySize, EDGE_SMEM);
    cudaFuncSetAttribute(agg_kernel,   cudaFuncAttributeMaxDynamicSharedMemorySize, AGG_SMEM);
    cudaFuncSetAttribute(pnode_kernel, cudaFuncAttributeMaxDynamicSharedMemorySize, PNODE_SMEM);

    const int NODE_TILES = NPAD / 128;  // 313

    zero_kernel<<<(NPAD * D / 4 + 255) / 256, 256>>>();
    ln_kernel<<<N_NODES / 8, 256>>>(nf, gam, bet);
    wprep_kernel<<<448, 256>>>(mw1, mw2, aw1, aw2);
    pnode_kernel<<<NODE_TILES, 256, PNODE_SMEM>>>();
    cnt_kernel<<<(N_EDGES + 255) / 256, 256>>>(src);
    edge_persist_kernel<<<152, 256, EDGE_SMEM>>>(ef, mb1, mb2, src, dst);
    agg_kernel<<<NODE_TILES, 256, AGG_SMEM>>>(nf, ab1, ab2, out);
}